// round 3
// baseline (speedup 1.0000x reference)
#include <cuda_runtime.h>

#define TT 16
#define NU 4096
#define EE 128
#define HH 128
#define G4 512
#define LPATH 32
#define NPATH 1024
#define NB 8
#define VOCAB 16384

// ---------------- device scratch (zero at load; invalid rows never written) ----------
__device__ int   g_tok_len[NU];
__device__ int   g_p_len[NPATH], g_p_fe[NPATH], g_p_off[NPATH], g_p_un[NPATH];
__device__ float g_VTf[VOCAB * G4], g_VTb[VOCAB * G4];   // vocab gate tables (bias baked in)
__device__ float g_PTf[NU * G4],    g_PTb[NU * G4];      // tokfeat gate tables (no bias)
__device__ float g_Hcat[TT * NU * 2 * HH];
__device__ float g_lin[TT * NU * EE];
__device__ float g_tokfeat[NU * EE];
__device__ float g_Hp[LPATH * NPATH * 2 * HH];
__device__ float g_WhT[4][HH * G4];                      // 0 tl_f, 1 tl_b, 2 pl_f, 3 pl_b
__device__ float g_zero[G4];                             // stays zero

// ---------------- setup kernels ----------------
__global__ void k_tok_len(const int* __restrict__ units) {
    int n = blockIdx.x * blockDim.x + threadIdx.x;
    if (n >= NU) return;
    int len = TT;
    for (int t = 0; t < TT; t++) if (units[t * NU + n] == 0) { len = t; break; }
    g_tok_len[n] = len;
}

__global__ void k_transpose4(const float* __restrict__ W0, const float* __restrict__ W1,
                             const float* __restrict__ W2, const float* __restrict__ W3) {
    int w = blockIdx.y;
    const float* W = (w == 0) ? W0 : (w == 1) ? W1 : (w == 2) ? W2 : W3;
    int idx = blockIdx.x * blockDim.x + threadIdx.x;
    if (idx >= G4 * HH) return;
    int j = idx >> 7, k = idx & 127;
    g_WhT[w][k * G4 + j] = W[idx];
}

__global__ void k_plen(const int* __restrict__ paths,
                       const int* __restrict__ upd, const int* __restrict__ ppd) {
    int p = blockIdx.x * blockDim.x + threadIdx.x;
    if (p >= NPATH) return;
    int dd = NB - 1, cum = 0;
    for (int i = 0; i < NB; i++) { int nx = cum + ppd[i]; if (p >= cum && p < nx) { dd = i; break; } cum = nx; }
    int off = 0;
    for (int i = 0; i < dd; i++) off += upd[i];
    int un = upd[dd];
    int fe = LPATH;
    for (int t = 0; t < LPATH; t++) if (paths[t * NPATH + p] == -1) { fe = t; break; }
    int plen = LPATH;
    for (int t = 0; t < LPATH; t++) {
        bool msk;
        if (t >= fe) msk = true;
        else { int v = paths[t * NPATH + p]; msk = (v < 0) || (v > un); }
        if (msk) { plen = t; break; }
    }
    g_p_len[p] = plen; g_p_fe[p] = fe; g_p_off[p] = off; g_p_un[p] = un;
}

// -------- NT GEMM + bias: C[m,n] = sum_k A[m,k]*W[n,k] + b[n]; M,N mult of 128, K of 16 ----
__global__ __launch_bounds__(256) void k_gemm_nt_bias(
    const float* __restrict__ A, const float* __restrict__ W,
    const float* __restrict__ bias, float* __restrict__ C, int M, int N, int K)
{
    __shared__ float sA[16][128];
    __shared__ float sB[16][128];
    const int tid = threadIdx.x;
    const int m0 = blockIdx.y * 128, n0 = blockIdx.x * 128;
    const int tx = tid & 15, ty = tid >> 4;

    float acc[8][8];
#pragma unroll
    for (int i = 0; i < 8; i++)
#pragma unroll
        for (int j = 0; j < 8; j++) acc[i][j] = 0.f;

    for (int k0 = 0; k0 < K; k0 += 16) {
#pragma unroll
        for (int i = 0; i < 2; i++) {
            int t4 = tid + i * 256;
            int row = t4 >> 2, kq = t4 & 3;
            float4 va = *reinterpret_cast<const float4*>(&A[(size_t)(m0 + row) * K + k0 + kq * 4]);
            sA[kq * 4 + 0][row] = va.x; sA[kq * 4 + 1][row] = va.y;
            sA[kq * 4 + 2][row] = va.z; sA[kq * 4 + 3][row] = va.w;
            float4 vb = *reinterpret_cast<const float4*>(&W[(size_t)(n0 + row) * K + k0 + kq * 4]);
            sB[kq * 4 + 0][row] = vb.x; sB[kq * 4 + 1][row] = vb.y;
            sB[kq * 4 + 2][row] = vb.z; sB[kq * 4 + 3][row] = vb.w;
        }
        __syncthreads();
#pragma unroll
        for (int kk = 0; kk < 16; kk++) {
            float4 a0 = *reinterpret_cast<const float4*>(&sA[kk][ty * 8]);
            float4 a1 = *reinterpret_cast<const float4*>(&sA[kk][ty * 8 + 4]);
            float4 b0 = *reinterpret_cast<const float4*>(&sB[kk][tx * 8]);
            float4 b1 = *reinterpret_cast<const float4*>(&sB[kk][tx * 8 + 4]);
            float a[8] = {a0.x, a0.y, a0.z, a0.w, a1.x, a1.y, a1.z, a1.w};
            float b[8] = {b0.x, b0.y, b0.z, b0.w, b1.x, b1.y, b1.z, b1.w};
#pragma unroll
            for (int i = 0; i < 8; i++)
#pragma unroll
                for (int j = 0; j < 8; j++) acc[i][j] += a[i] * b[j];
        }
        __syncthreads();
    }
    float bi[8];
#pragma unroll
    for (int j = 0; j < 8; j++) bi[j] = bias[n0 + tx * 8 + j];
#pragma unroll
    for (int i = 0; i < 8; i++) {
        float4 o0 = make_float4(acc[i][0] + bi[0], acc[i][1] + bi[1], acc[i][2] + bi[2], acc[i][3] + bi[3]);
        float4 o1 = make_float4(acc[i][4] + bi[4], acc[i][5] + bi[5], acc[i][6] + bi[6], acc[i][7] + bi[7]);
        size_t off = (size_t)(m0 + ty * 8 + i) * N + n0 + tx * 8;
        *reinterpret_cast<float4*>(&C[off]) = o0;
        *reinterpret_cast<float4*>(&C[off + 4]) = o1;
    }
}

// ---------------- persistent BiLSTM with table-gathered input gates ----------------
__device__ __forceinline__ float sigm(float x) { return 1.f / (1.f + expf(-x)); }

// MODE 0: token (idxmat=units, tab=VT with bias baked in, lens=g_tok_len)
// MODE 1: path  (idxmat=paths, tab=PT no bias, bias added here, keep-masking, lens=g_p_len)
template <int MODE, int TSTEPS, int NSEQ>
__global__ __launch_bounds__(256) void k_lstm(
    const int* __restrict__ idxmat,
    const float* __restrict__ tab_f, const float* __restrict__ tab_b,
    const float* __restrict__ bias_f, const float* __restrict__ bias_b,
    float* __restrict__ Hout)
{
    const int ROWS = 16, RPT = 4;
    const int dir = blockIdx.y;
    const float* __restrict__ tab = dir ? tab_b : tab_f;
    const float* __restrict__ WhT = g_WhT[2 * MODE + dir];
    const int n0 = blockIdx.x * ROWS;

    __shared__ float hs[ROWS][HH];
    __shared__ float wst[16][G4];
    __shared__ float sbias[G4];
    __shared__ int slen[ROWS], sfe[ROWS], soff[ROWS], sun[ROWS];

    const int tid = threadIdx.x, jt = tid & 63, rt = tid >> 6;
    const int e0 = jt * 2, r0 = rt * RPT;

    if (MODE == 1) {
        const float* b = dir ? bias_b : bias_f;
        for (int i = tid; i < G4; i += 256) sbias[i] = b[i];
    }
    float c[RPT][2];
#pragma unroll
    for (int r = 0; r < RPT; r++) {
        c[r][0] = 0.f; c[r][1] = 0.f;
        hs[r0 + r][e0] = 0.f; hs[r0 + r][e0 + 1] = 0.f;
    }
    if (tid < ROWS) {
        int n = n0 + tid;
        slen[tid] = MODE ? g_p_len[n] : g_tok_len[n];
        if (MODE) { sfe[tid] = g_p_fe[n]; soff[tid] = g_p_off[n]; sun[tid] = g_p_un[n]; }
    }
    __syncthreads();

    for (int s = 0; s < TSTEPS; s++) {
        float acc[RPT][8];
#pragma unroll
        for (int r = 0; r < RPT; r++)
#pragma unroll
            for (int j = 0; j < 8; j++) acc[r][j] = 0.f;

        for (int kc = 0; kc < HH; kc += 16) {
            __syncthreads();
#pragma unroll
            for (int i = 0; i < 8; i++) {
                int t4 = tid + i * 256;
                int kk = t4 >> 7, c4 = t4 & 127;
                *reinterpret_cast<float4*>(&wst[kk][c4 * 4]) =
                    *reinterpret_cast<const float4*>(&WhT[(size_t)(kc + kk) * G4 + c4 * 4]);
            }
            __syncthreads();
#pragma unroll
            for (int kk = 0; kk < 16; kk++) {
                float2 w0 = *reinterpret_cast<const float2*>(&wst[kk][e0]);
                float2 w1 = *reinterpret_cast<const float2*>(&wst[kk][128 + e0]);
                float2 w2 = *reinterpret_cast<const float2*>(&wst[kk][256 + e0]);
                float2 w3 = *reinterpret_cast<const float2*>(&wst[kk][384 + e0]);
#pragma unroll
                for (int r = 0; r < RPT; r++) {
                    float hv = hs[r0 + r][kc + kk];
                    acc[r][0] += hv * w0.x; acc[r][1] += hv * w0.y;
                    acc[r][2] += hv * w1.x; acc[r][3] += hv * w1.y;
                    acc[r][4] += hv * w2.x; acc[r][5] += hv * w2.y;
                    acc[r][6] += hv * w3.x; acc[r][7] += hv * w3.y;
                }
            }
        }

        float hnew[RPT][2];
#pragma unroll
        for (int r = 0; r < RPT; r++) {
            int rr = r0 + r, n = n0 + rr, len = slen[rr];
            int gi = dir ? min(max(len - 1 - s, 0), TSTEPS - 1) : s;
            float gv[8];
            if (MODE == 0) {
                int id = idxmat[(size_t)gi * NSEQ + n];
                const float* grow = tab + (size_t)id * G4;
                float2 a0 = *reinterpret_cast<const float2*>(&grow[e0]);
                float2 a1 = *reinterpret_cast<const float2*>(&grow[128 + e0]);
                float2 a2 = *reinterpret_cast<const float2*>(&grow[256 + e0]);
                float2 a3 = *reinterpret_cast<const float2*>(&grow[384 + e0]);
                gv[0] = a0.x; gv[1] = a0.y; gv[2] = a1.x; gv[3] = a1.y;
                gv[4] = a2.x; gv[5] = a2.y; gv[6] = a3.x; gv[7] = a3.y;
            } else {
                int pl = idxmat[(size_t)gi * NSEQ + n];
                bool keep = (gi < sfe[rr]) && (pl >= 0) && (pl < sun[rr]);
                float2 b0 = *reinterpret_cast<const float2*>(&sbias[e0]);
                float2 b1 = *reinterpret_cast<const float2*>(&sbias[128 + e0]);
                float2 b2 = *reinterpret_cast<const float2*>(&sbias[256 + e0]);
                float2 b3 = *reinterpret_cast<const float2*>(&sbias[384 + e0]);
                gv[0] = b0.x; gv[1] = b0.y; gv[2] = b1.x; gv[3] = b1.y;
                gv[4] = b2.x; gv[5] = b2.y; gv[6] = b3.x; gv[7] = b3.y;
                if (keep) {
                    int gidx = min(pl + soff[rr], NU - 1);
                    const float* grow = tab + (size_t)gidx * G4;
                    float2 t0 = *reinterpret_cast<const float2*>(&grow[e0]);
                    float2 t1 = *reinterpret_cast<const float2*>(&grow[128 + e0]);
                    float2 t2 = *reinterpret_cast<const float2*>(&grow[256 + e0]);
                    float2 t3 = *reinterpret_cast<const float2*>(&grow[384 + e0]);
                    gv[0] += t0.x; gv[1] += t0.y; gv[2] += t1.x; gv[3] += t1.y;
                    gv[4] += t2.x; gv[5] += t2.y; gv[6] += t3.x; gv[7] += t3.y;
                }
            }
#pragma unroll
            for (int u = 0; u < 2; u++) {
                float iv = acc[r][0 + u] + gv[0 + u];
                float fv = acc[r][2 + u] + gv[2 + u];
                float gg = acc[r][4 + u] + gv[4 + u];
                float ov = acc[r][6 + u] + gv[6 + u];
                float cn = sigm(fv) * c[r][u] + sigm(iv) * tanhf(gg);
                c[r][u] = cn;
                hnew[r][u] = sigm(ov) * tanhf(cn);
            }
            if (s < len) {
                int wi = dir ? (len - 1 - s) : s;
                *reinterpret_cast<float2*>(&Hout[((size_t)wi * NSEQ + n) * (2 * HH) + dir * HH + e0]) =
                    make_float2(hnew[r][0], hnew[r][1]);
            } else if (dir == 0) {
                float2 z = make_float2(0.f, 0.f);
                *reinterpret_cast<float2*>(&Hout[((size_t)s * NSEQ + n) * (2 * HH) + e0]) = z;
                *reinterpret_cast<float2*>(&Hout[((size_t)s * NSEQ + n) * (2 * HH) + HH + e0]) = z;
            }
        }
        __syncthreads();
#pragma unroll
        for (int r = 0; r < RPT; r++) {
            hs[r0 + r][e0]     = hnew[r][0];
            hs[r0 + r][e0 + 1] = hnew[r][1];
        }
    }
}

// ---------------- attention pooling: 1 warp per sequence ----------------
__global__ void k_attn(const float* __restrict__ ln_g, const float* __restrict__ ln_b,
                       const float* __restrict__ attn_w, const float* __restrict__ attn_bp) {
    int gwarp = (blockIdx.x * blockDim.x + threadIdx.x) >> 5;
    int lane = threadIdx.x & 31;
    if (gwarp >= NU) return;
    int n = gwarp, len = g_tok_len[n];

    float gg[4], bb[4], aw[4];
#pragma unroll
    for (int q = 0; q < 4; q++) {
        int e = lane + 32 * q;
        gg[q] = ln_g[e]; bb[q] = ln_b[e]; aw[q] = attn_w[e];
    }
    float ab = attn_bp[0];

    float sc[TT], smax = -1e30f;
#pragma unroll
    for (int t = 0; t < TT; t++) {
        sc[t] = -1e30f;
        if (t < len) {
            float o[4], lsum = 0.f;
#pragma unroll
            for (int q = 0; q < 4; q++) {
                o[q] = g_lin[((size_t)t * NU + n) * EE + lane + 32 * q];
                lsum += o[q];
            }
#pragma unroll
            for (int off = 16; off; off >>= 1) lsum += __shfl_xor_sync(0xffffffffu, lsum, off);
            float mean = lsum * (1.f / 128.f);
            float vs = 0.f;
#pragma unroll
            for (int q = 0; q < 4; q++) { float d = o[q] - mean; vs += d * d; }
#pragma unroll
            for (int off = 16; off; off >>= 1) vs += __shfl_xor_sync(0xffffffffu, vs, off);
            float inv = rsqrtf(vs * (1.f / 128.f) + 1e-5f);
            float ssum = 0.f;
#pragma unroll
            for (int q = 0; q < 4; q++)
                ssum += tanhf((o[q] - mean) * inv * gg[q] + bb[q]) * aw[q];
#pragma unroll
            for (int off = 16; off; off >>= 1) ssum += __shfl_xor_sync(0xffffffffu, ssum, off);
            sc[t] = ssum + ab;
            smax = fmaxf(smax, sc[t]);
        }
    }
    float den = 0.f, wts[TT];
#pragma unroll
    for (int t = 0; t < TT; t++) {
        wts[t] = (t < len) ? expf(sc[t] - smax) : 0.f;
        den += wts[t];
    }
    float invden = 1.f / den;
    float accq[4] = {0.f, 0.f, 0.f, 0.f};
#pragma unroll
    for (int t = 0; t < TT; t++) {
        if (t < len) {
            float wt = wts[t] * invden;
#pragma unroll
            for (int q = 0; q < 4; q++)
                accq[q] += wt * g_lin[((size_t)t * NU + n) * EE + lane + 32 * q];
        }
    }
#pragma unroll
    for (int q = 0; q < 4; q++) g_tokfeat[(size_t)n * EE + lane + 32 * q] = accq[q];
}

// ---------------- host launcher ----------------
extern "C" void kernel_launch(void* const* d_in, const int* in_sizes, int n_in,
                              void* d_out, int out_size) {
    const int*   units  = (const int*)d_in[0];
    const int*   paths  = (const int*)d_in[1];
    const int*   upd    = (const int*)d_in[2];
    const int*   ppd    = (const int*)d_in[3];
    const float* emb    = (const float*)d_in[4];
    const float* tl_Wif = (const float*)d_in[5];
    const float* tl_Whf = (const float*)d_in[6];
    const float* tl_bf  = (const float*)d_in[7];
    const float* tl_Wib = (const float*)d_in[8];
    const float* tl_Whb = (const float*)d_in[9];
    const float* tl_bb  = (const float*)d_in[10];
    const float* lin_W  = (const float*)d_in[11];
    const float* lin_b  = (const float*)d_in[12];
    const float* ln_g   = (const float*)d_in[13];
    const float* ln_bv  = (const float*)d_in[14];
    const float* attn_w = (const float*)d_in[15];
    const float* attn_b = (const float*)d_in[16];
    const float* pl_Wif = (const float*)d_in[17];
    const float* pl_Whf = (const float*)d_in[18];
    const float* pl_bf  = (const float*)d_in[19];
    const float* pl_Wib = (const float*)d_in[20];
    const float* pl_Whb = (const float*)d_in[21];
    const float* pl_bb  = (const float*)d_in[22];
    const float* ul_W   = (const float*)d_in[23];
    const float* ul_b   = (const float*)d_in[24];
    float* out = (float*)d_out;

    void *pVTf, *pVTb, *pPTf, *pPTb, *pHcat, *pLin, *pTokfeat, *pHp, *pZero;
    cudaGetSymbolAddress(&pVTf, g_VTf);
    cudaGetSymbolAddress(&pVTb, g_VTb);
    cudaGetSymbolAddress(&pPTf, g_PTf);
    cudaGetSymbolAddress(&pPTb, g_PTb);
    cudaGetSymbolAddress(&pHcat, g_Hcat);
    cudaGetSymbolAddress(&pLin, g_lin);
    cudaGetSymbolAddress(&pTokfeat, g_tokfeat);
    cudaGetSymbolAddress(&pHp, g_Hp);
    cudaGetSymbolAddress(&pZero, g_zero);

    // setup (independent)
    k_tok_len<<<NU / 256, 256>>>(units);
    k_transpose4<<<dim3((G4 * HH + 255) / 256, 4), 256>>>(tl_Whf, tl_Whb, pl_Whf, pl_Whb);
    k_plen<<<NPATH / 256, 256>>>(paths, upd, ppd);

    // vocab gate tables: VT = emb @ Wi^T + b   (16384 x 512)
    k_gemm_nt_bias<<<dim3(G4 / 128, VOCAB / 128), 256>>>(emb, tl_Wif, tl_bf, (float*)pVTf, VOCAB, G4, EE);
    k_gemm_nt_bias<<<dim3(G4 / 128, VOCAB / 128), 256>>>(emb, tl_Wib, tl_bb, (float*)pVTb, VOCAB, G4, EE);

    // token BiLSTM -> Hcat (16,4096,256)
    k_lstm<0, TT, NU><<<dim3(NU / 16, 2), 256>>>(units, (const float*)pVTf, (const float*)pVTb,
                                                 nullptr, nullptr, (float*)pHcat);

    // lin = Hcat @ lin_W^T + lin_b   (65536 x 128)
    k_gemm_nt_bias<<<dim3(EE / 128, TT * NU / 128), 256>>>((const float*)pHcat, lin_W, lin_b,
                                                           (float*)pLin, TT * NU, EE, 2 * HH);

    // attention pooling -> tokfeat (4096,128)
    k_attn<<<(NU * 32) / 256, 256>>>(ln_g, ln_bv, attn_w, attn_b);

    // path gate tables: PT = tokfeat @ pl_Wi^T (no bias)  (4096 x 512)
    k_gemm_nt_bias<<<dim3(G4 / 128, NU / 128), 256>>>((const float*)pTokfeat, pl_Wif, (const float*)pZero,
                                                      (float*)pPTf, NU, G4, EE);
    k_gemm_nt_bias<<<dim3(G4 / 128, NU / 128), 256>>>((const float*)pTokfeat, pl_Wib, (const float*)pZero,
                                                      (float*)pPTb, NU, G4, EE);

    // path BiLSTM -> Hp (32,1024,256)
    k_lstm<1, LPATH, NPATH><<<dim3(NPATH / 16, 2), 256>>>(paths, (const float*)pPTf, (const float*)pPTb,
                                                          pl_bf, pl_bb, (float*)pHp);

    // out = Hp @ ul_W^T + ul_b   (32768 x 128)
    k_gemm_nt_bias<<<dim3(EE / 128, LPATH * NPATH / 128), 256>>>((const float*)pHp, ul_W, ul_b,
                                                                 out, LPATH * NPATH, EE, 2 * HH);
}

// round 6
// speedup vs baseline: 1.0371x; 1.0371x over previous
#include <cuda_runtime.h>
#include <cuda_bf16.h>
#include <cstdint>

#define TT 16
#define NU 4096
#define EE 128
#define HH 128
#define G4 512
#define LPATH 32
#define NPATH 1024
#define NB 8
#define VOCAB 16384

// ================= warp-MMA helpers (non-arch-suffixed PTX, sm_80+) =================
__device__ __forceinline__ uint32_t smem_to_u32(const void* p) {
    uint32_t a;
    asm("{ .reg .u64 t; cvta.to.shared.u64 t, %1; cvt.u32.u64 %0, t; }" : "=r"(a) : "l"(p));
    return a;
}
#define LDSM_X4(r, addr) \
    asm volatile("ldmatrix.sync.aligned.m8n8.x4.shared.b16 {%0,%1,%2,%3}, [%4];" \
        : "=r"((r)[0]), "=r"((r)[1]), "=r"((r)[2]), "=r"((r)[3]) : "r"(addr))

__device__ __forceinline__ void mma16816(float* c, const uint32_t* a, uint32_t b0, uint32_t b1) {
    asm volatile("mma.sync.aligned.m16n8k16.row.col.f32.bf16.bf16.f32 "
        "{%0,%1,%2,%3}, {%4,%5,%6,%7}, {%8,%9}, {%0,%1,%2,%3};"
        : "+f"(c[0]), "+f"(c[1]), "+f"(c[2]), "+f"(c[3])
        : "r"(a[0]), "r"(a[1]), "r"(a[2]), "r"(a[3]), "r"(b0), "r"(b1));
}

// ================= device scratch =================
__device__ int   g_tok_len[NU];
__device__ int   g_p_len[NPATH], g_p_fe[NPATH], g_p_off[NPATH], g_p_un[NPATH];
__device__ float g_VTf[VOCAB * G4], g_VTb[VOCAB * G4];
__device__ float g_PTf[NU * G4],    g_PTb[NU * G4];
__device__ float g_lin[TT * NU * EE];
__device__ float g_WhT[4][HH * G4];
__device__ float g_zero[G4];

// bf16 hi/lo operand buffers (producers write these directly)
__device__ __nv_bfloat16 g_emb_h[VOCAB * EE],  g_emb_l[VOCAB * EE];
__device__ __nv_bfloat16 g_Hcat_h[TT * NU * 2 * HH], g_Hcat_l[TT * NU * 2 * HH];
__device__ __nv_bfloat16 g_tf_h[NU * EE], g_tf_l[NU * EE];
__device__ __nv_bfloat16 g_Hp_h[LPATH * NPATH * 2 * HH], g_Hp_l[LPATH * NPATH * 2 * HH];
__device__ __nv_bfloat16 g_Wih[4][G4 * EE], g_Wil[4][G4 * EE];
__device__ __nv_bfloat16 g_W2h[2][EE * 2 * HH], g_W2l[2][EE * 2 * HH];

// ================= setup kernels =================
__global__ void k_tok_len(const int* __restrict__ units) {
    int n = blockIdx.x * blockDim.x + threadIdx.x;
    if (n >= NU) return;
    int len = TT;
    for (int t = 0; t < TT; t++) if (units[t * NU + n] == 0) { len = t; break; }
    g_tok_len[n] = len;
}

__global__ void k_transpose4(const float* __restrict__ W0, const float* __restrict__ W1,
                             const float* __restrict__ W2, const float* __restrict__ W3) {
    int w = blockIdx.y;
    const float* W = (w == 0) ? W0 : (w == 1) ? W1 : (w == 2) ? W2 : W3;
    int idx = blockIdx.x * blockDim.x + threadIdx.x;
    if (idx >= G4 * HH) return;
    int j = idx >> 7, k = idx & 127;
    g_WhT[w][k * G4 + j] = W[idx];
}

__global__ void k_plen(const int* __restrict__ paths,
                       const int* __restrict__ upd, const int* __restrict__ ppd) {
    int p = blockIdx.x * blockDim.x + threadIdx.x;
    if (p >= NPATH) return;
    int dd = NB - 1, cum = 0;
    for (int i = 0; i < NB; i++) { int nx = cum + ppd[i]; if (p >= cum && p < nx) { dd = i; break; } cum = nx; }
    int off = 0;
    for (int i = 0; i < dd; i++) off += upd[i];
    int un = upd[dd];
    int fe = LPATH;
    for (int t = 0; t < LPATH; t++) if (paths[t * NPATH + p] == -1) { fe = t; break; }
    int plen = LPATH;
    for (int t = 0; t < LPATH; t++) {
        bool msk;
        if (t >= fe) msk = true;
        else { int v = paths[t * NPATH + p]; msk = (v < 0) || (v > un); }
        if (msk) { plen = t; break; }
    }
    g_p_len[p] = plen; g_p_fe[p] = fe; g_p_off[p] = off; g_p_un[p] = un;
}

// fp32 -> bf16 hi + lo residual (weights & emb)
__global__ void k_hilo(const float* __restrict__ src, __nv_bfloat16* __restrict__ hi,
                       __nv_bfloat16* __restrict__ lo, int n4) {
    int i = blockIdx.x * blockDim.x + threadIdx.x;
    if (i >= n4) return;
    float4 v = reinterpret_cast<const float4*>(src)[i];
    __nv_bfloat16 h0 = __float2bfloat16(v.x), h1 = __float2bfloat16(v.y);
    __nv_bfloat16 h2 = __float2bfloat16(v.z), h3 = __float2bfloat16(v.w);
    __nv_bfloat16 l0 = __float2bfloat16(v.x - __bfloat162float(h0));
    __nv_bfloat16 l1 = __float2bfloat16(v.y - __bfloat162float(h1));
    __nv_bfloat16 l2 = __float2bfloat16(v.z - __bfloat162float(h2));
    __nv_bfloat16 l3 = __float2bfloat16(v.w - __bfloat162float(h3));
    __nv_bfloat162* H = reinterpret_cast<__nv_bfloat162*>(hi);
    __nv_bfloat162* L = reinterpret_cast<__nv_bfloat162*>(lo);
    H[2 * i] = __nv_bfloat162(h0, h1); H[2 * i + 1] = __nv_bfloat162(h2, h3);
    L[2 * i] = __nv_bfloat162(l0, l1); L[2 * i + 1] = __nv_bfloat162(l2, l3);
}

// ================= warp-MMA split-bf16 GEMM =================
// C[m,n] = sum_k A[m,k]*W[n,k] + bias[n]; 128x128 block tile, 8 warps (4m x 2n),
// warp tile 32x64. K chunked by 64 through padded smem (stride 72 bf16).
// 3 passes: Ah*Bh + Al*Bh + Ah*Bl.
template <int K>
__global__ __launch_bounds__(256) void k_mm2(
    const __nv_bfloat16* __restrict__ Ah, const __nv_bfloat16* __restrict__ Al,
    const __nv_bfloat16* __restrict__ Bh, const __nv_bfloat16* __restrict__ Bl,
    const float* __restrict__ bias, float* __restrict__ C, int Ntot)
{
    constexpr int LDS = 72;
    extern __shared__ __nv_bfloat16 sm[];
    __nv_bfloat16* sAh = sm;
    __nv_bfloat16* sAl = sAh + 128 * LDS;
    __nv_bfloat16* sBh = sAl + 128 * LDS;
    __nv_bfloat16* sBl = sBh + 128 * LDS;

    const int tid = threadIdx.x, lane = tid & 31, wid = tid >> 5;
    const int m0 = blockIdx.y * 128, n0 = blockIdx.x * 128;
    const int wm = (wid & 3) * 32, wn = (wid >> 2) * 64;
    const int g = lane >> 2, tg = lane & 3;
    const int seg = lane >> 3, i8 = lane & 7;

    const uint32_t sAh_b = smem_to_u32(sAh), sAl_b = smem_to_u32(sAl);
    const uint32_t sBh_b = smem_to_u32(sBh), sBl_b = smem_to_u32(sBl);

    float acc[2][8][4];
#pragma unroll
    for (int im = 0; im < 2; im++)
#pragma unroll
        for (int jn = 0; jn < 8; jn++)
#pragma unroll
            for (int q = 0; q < 4; q++) acc[im][jn][q] = 0.f;

    for (int kc = 0; kc < K; kc += 64) {
        if (kc) __syncthreads();
        {
            const __nv_bfloat16* srcs[4] = {Ah, Al, Bh, Bl};
            __nv_bfloat16* dsts[4] = {sAh, sAl, sBh, sBl};
            const int r0s[4] = {m0, m0, n0, n0};
#pragma unroll
            for (int t = 0; t < 4; t++) {
                for (int v = tid; v < 1024; v += 256) {
                    int row = v >> 3, q = (v & 7) * 8;
                    *reinterpret_cast<uint4*>(dsts[t] + row * LDS + q) =
                        *reinterpret_cast<const uint4*>(srcs[t] + (size_t)(r0s[t] + row) * K + kc + q);
                }
            }
        }
        __syncthreads();

#pragma unroll
        for (int ks = 0; ks < 4; ks++) {
            const int k0 = ks * 16;
            uint32_t ah[2][4], al[2][4];
#pragma unroll
            for (int im = 0; im < 2; im++) {
                int arow = wm + im * 16 + (seg & 1) * 8 + i8;
                int acol = k0 + (seg >> 1) * 8;
                LDSM_X4(ah[im], sAh_b + (uint32_t)(arow * LDS + acol) * 2u);
                LDSM_X4(al[im], sAl_b + (uint32_t)(arow * LDS + acol) * 2u);
            }
#pragma unroll
            for (int ip = 0; ip < 4; ip++) {
                int brow = wn + ip * 16 + (seg >> 1) * 8 + i8;
                int bcol = k0 + (seg & 1) * 8;
                uint32_t bh4[4], bl4[4];
                LDSM_X4(bh4, sBh_b + (uint32_t)(brow * LDS + bcol) * 2u);
                LDSM_X4(bl4, sBl_b + (uint32_t)(brow * LDS + bcol) * 2u);
#pragma unroll
                for (int im = 0; im < 2; im++) {
#pragma unroll
                    for (int hf = 0; hf < 2; hf++) {
                        float* c = acc[im][ip * 2 + hf];
                        mma16816(c, ah[im], bh4[2 * hf], bh4[2 * hf + 1]);
                        mma16816(c, al[im], bh4[2 * hf], bh4[2 * hf + 1]);
                        mma16816(c, ah[im], bl4[2 * hf], bl4[2 * hf + 1]);
                    }
                }
            }
        }
    }

    // epilogue
#pragma unroll
    for (int im = 0; im < 2; im++) {
#pragma unroll
        for (int jn = 0; jn < 8; jn++) {
            int col = n0 + wn + jn * 8 + tg * 2;
            float b0v = bias[col], b1v = bias[col + 1];
            int row0 = m0 + wm + im * 16 + g;
            float2 v0 = make_float2(acc[im][jn][0] + b0v, acc[im][jn][1] + b1v);
            float2 v1 = make_float2(acc[im][jn][2] + b0v, acc[im][jn][3] + b1v);
            *reinterpret_cast<float2*>(C + (size_t)row0 * Ntot + col) = v0;
            *reinterpret_cast<float2*>(C + (size_t)(row0 + 8) * Ntot + col) = v1;
        }
    }
}

// ================= persistent BiLSTM (SIMT), bf16 hi/lo output =================
__device__ __forceinline__ float sigm(float x) { return 1.f / (1.f + expf(-x)); }

template <int MODE, int TSTEPS, int NSEQ, int ROWS, int THREADS>
__global__ __launch_bounds__(THREADS) void k_lstm(
    const int* __restrict__ idxmat,
    const float* __restrict__ tab_f, const float* __restrict__ tab_b,
    const float* __restrict__ bias_f, const float* __restrict__ bias_b,
    __nv_bfloat16* __restrict__ Hh, __nv_bfloat16* __restrict__ Hl)
{
    constexpr int NW = THREADS / 32, RPT = ROWS / NW;
    extern __shared__ char dsm[];
    float* hs    = reinterpret_cast<float*>(dsm);       // [ROWS][HH]
    float* wst   = hs + ROWS * HH;                      // [16][G4]
    float* sbias = wst + 16 * G4;                       // [G4]
    int* slen = reinterpret_cast<int*>(sbias + G4);
    int* sfe = slen + ROWS; int* soff = sfe + ROWS; int* sun = soff + ROWS;

    const int dir = blockIdx.y;
    const float* __restrict__ tab = dir ? tab_b : tab_f;
    const float* __restrict__ WhT = g_WhT[2 * MODE + dir];
    const int n0 = blockIdx.x * ROWS;
    const int tid = threadIdx.x, jt = tid & 31, rt = tid >> 5;
    const int e0 = jt * 4, r0 = rt * RPT;

    if (MODE == 1) {
        const float* b = dir ? bias_b : bias_f;
        for (int i = tid; i < G4; i += THREADS) sbias[i] = b[i];
    }
    float c[RPT][4];
#pragma unroll
    for (int r = 0; r < RPT; r++) {
#pragma unroll
        for (int u = 0; u < 4; u++) c[r][u] = 0.f;
        *reinterpret_cast<float4*>(&hs[(r0 + r) * HH + e0]) = make_float4(0.f, 0.f, 0.f, 0.f);
    }
    if (tid < ROWS) {
        int n = n0 + tid;
        slen[tid] = MODE ? g_p_len[n] : g_tok_len[n];
        if (MODE) { sfe[tid] = g_p_fe[n]; soff[tid] = g_p_off[n]; sun[tid] = g_p_un[n]; }
    }
    __syncthreads();

    for (int s = 0; s < TSTEPS; s++) {
        float acc[RPT][16];
#pragma unroll
        for (int r = 0; r < RPT; r++)
#pragma unroll
            for (int j = 0; j < 16; j++) acc[r][j] = 0.f;

        for (int kc = 0; kc < HH; kc += 16) {
            __syncthreads();
            for (int i = tid; i < 2048; i += THREADS) {
                int kk = i >> 7, c4 = i & 127;
                reinterpret_cast<float4*>(&wst[kk * G4])[c4] =
                    reinterpret_cast<const float4*>(&WhT[(size_t)(kc + kk) * G4])[c4];
            }
            __syncthreads();
#pragma unroll
            for (int kk = 0; kk < 16; kk++) {
                float4 w0 = *reinterpret_cast<const float4*>(&wst[kk * G4 + e0]);
                float4 w1 = *reinterpret_cast<const float4*>(&wst[kk * G4 + 128 + e0]);
                float4 w2 = *reinterpret_cast<const float4*>(&wst[kk * G4 + 256 + e0]);
                float4 w3 = *reinterpret_cast<const float4*>(&wst[kk * G4 + 384 + e0]);
#pragma unroll
                for (int r = 0; r < RPT; r++) {
                    float hv = hs[(r0 + r) * HH + kc + kk];
                    acc[r][0] += hv * w0.x; acc[r][1]  += hv * w0.y; acc[r][2]  += hv * w0.z; acc[r][3]  += hv * w0.w;
                    acc[r][4] += hv * w1.x; acc[r][5]  += hv * w1.y; acc[r][6]  += hv * w1.z; acc[r][7]  += hv * w1.w;
                    acc[r][8] += hv * w2.x; acc[r][9]  += hv * w2.y; acc[r][10] += hv * w2.z; acc[r][11] += hv * w2.w;
                    acc[r][12]+= hv * w3.x; acc[r][13] += hv * w3.y; acc[r][14] += hv * w3.z; acc[r][15] += hv * w3.w;
                }
            }
        }

        float hnew[RPT][4];
#pragma unroll
        for (int r = 0; r < RPT; r++) {
            int rr = r0 + r, n = n0 + rr, len = slen[rr];
            int gi = dir ? min(max(len - 1 - s, 0), TSTEPS - 1) : s;
            float gv[16];
            if (MODE == 0) {
                int id = idxmat[(size_t)gi * NSEQ + n];
                const float* grow = tab + (size_t)id * G4;
                float4 a0 = *reinterpret_cast<const float4*>(&grow[e0]);
                float4 a1 = *reinterpret_cast<const float4*>(&grow[128 + e0]);
                float4 a2 = *reinterpret_cast<const float4*>(&grow[256 + e0]);
                float4 a3 = *reinterpret_cast<const float4*>(&grow[384 + e0]);
                gv[0]=a0.x; gv[1]=a0.y; gv[2]=a0.z; gv[3]=a0.w;
                gv[4]=a1.x; gv[5]=a1.y; gv[6]=a1.z; gv[7]=a1.w;
                gv[8]=a2.x; gv[9]=a2.y; gv[10]=a2.z; gv[11]=a2.w;
                gv[12]=a3.x; gv[13]=a3.y; gv[14]=a3.z; gv[15]=a3.w;
            } else {
                int pl = idxmat[(size_t)gi * NSEQ + n];
                bool keep = (gi < sfe[rr]) && (pl >= 0) && (pl < sun[rr]);
                float4 b0 = *reinterpret_cast<const float4*>(&sbias[e0]);
                float4 b1 = *reinterpret_cast<const float4*>(&sbias[128 + e0]);
                float4 b2 = *reinterpret_cast<const float4*>(&sbias[256 + e0]);
                float4 b3 = *reinterpret_cast<const float4*>(&sbias[384 + e0]);
                gv[0]=b0.x; gv[1]=b0.y; gv[2]=b0.z; gv[3]=b0.w;
                gv[4]=b1.x; gv[5]=b1.y; gv[6]=b1.z; gv[7]=b1.w;
                gv[8]=b2.x; gv[9]=b2.y; gv[10]=b2.z; gv[11]=b2.w;
                gv[12]=b3.x; gv[13]=b3.y; gv[14]=b3.z; gv[15]=b3.w;
                if (keep) {
                    int gidx = min(pl + soff[rr], NU - 1);
                    const float* grow = tab + (size_t)gidx * G4;
                    float4 t0 = *reinterpret_cast<const float4*>(&grow[e0]);
                    float4 t1 = *reinterpret_cast<const float4*>(&grow[128 + e0]);
                    float4 t2 = *reinterpret_cast<const float4*>(&grow[256 + e0]);
                    float4 t3 = *reinterpret_cast<const float4*>(&grow[384 + e0]);
                    gv[0]+=t0.x; gv[1]+=t0.y; gv[2]+=t0.z; gv[3]+=t0.w;
                    gv[4]+=t1.x; gv[5]+=t1.y; gv[6]+=t1.z; gv[7]+=t1.w;
                    gv[8]+=t2.x; gv[9]+=t2.y; gv[10]+=t2.z; gv[11]+=t2.w;
                    gv[12]+=t3.x; gv[13]+=t3.y; gv[14]+=t3.z; gv[15]+=t3.w;
                }
            }
#pragma unroll
            for (int u = 0; u < 4; u++) {
                float iv = acc[r][u]      + gv[u];
                float fv = acc[r][4 + u]  + gv[4 + u];
                float gg = acc[r][8 + u]  + gv[8 + u];
                float ov = acc[r][12 + u] + gv[12 + u];
                float cn = sigm(fv) * c[r][u] + sigm(iv) * tanhf(gg);
                c[r][u] = cn;
                hnew[r][u] = sigm(ov) * tanhf(cn);
            }
            if (s < len) {
                int wi = dir ? (len - 1 - s) : s;
                size_t base = ((size_t)wi * NSEQ + n) * (2 * HH) + dir * HH + e0;
                __nv_bfloat16 hb[4], lb[4];
#pragma unroll
                for (int u = 0; u < 4; u++) {
                    hb[u] = __float2bfloat16(hnew[r][u]);
                    lb[u] = __float2bfloat16(hnew[r][u] - __bfloat162float(hb[u]));
                }
                *reinterpret_cast<uint2*>(Hh + base) = *reinterpret_cast<uint2*>(hb);
                *reinterpret_cast<uint2*>(Hl + base) = *reinterpret_cast<uint2*>(lb);
            } else if (dir == 0) {
                uint2 z = make_uint2(0u, 0u);
                size_t b0 = ((size_t)s * NSEQ + n) * (2 * HH) + e0;
                *reinterpret_cast<uint2*>(Hh + b0) = z;
                *reinterpret_cast<uint2*>(Hl + b0) = z;
                *reinterpret_cast<uint2*>(Hh + b0 + HH) = z;
                *reinterpret_cast<uint2*>(Hl + b0 + HH) = z;
            }
        }
        __syncthreads();
#pragma unroll
        for (int r = 0; r < RPT; r++)
            *reinterpret_cast<float4*>(&hs[(r0 + r) * HH + e0]) =
                make_float4(hnew[r][0], hnew[r][1], hnew[r][2], hnew[r][3]);
    }
}

// ================= attention pooling (writes tf hi/lo) =================
__global__ void k_attn(const float* __restrict__ ln_g, const float* __restrict__ ln_b,
                       const float* __restrict__ attn_w, const float* __restrict__ attn_bp) {
    int gwarp = (blockIdx.x * blockDim.x + threadIdx.x) >> 5;
    int lane = threadIdx.x & 31;
    if (gwarp >= NU) return;
    int n = gwarp, len = g_tok_len[n];

    float gg[4], bb[4], aw[4];
#pragma unroll
    for (int q = 0; q < 4; q++) {
        int e = lane + 32 * q;
        gg[q] = ln_g[e]; bb[q] = ln_b[e]; aw[q] = attn_w[e];
    }
    float ab = attn_bp[0];

    float sc[TT], smax = -1e30f;
#pragma unroll
    for (int t = 0; t < TT; t++) {
        sc[t] = -1e30f;
        if (t < len) {
            float o[4], lsum = 0.f;
#pragma unroll
            for (int q = 0; q < 4; q++) {
                o[q] = g_lin[((size_t)t * NU + n) * EE + lane + 32 * q];
                lsum += o[q];
            }
#pragma unroll
            for (int off = 16; off; off >>= 1) lsum += __shfl_xor_sync(0xffffffffu, lsum, off);
            float mean = lsum * (1.f / 128.f);
            float vs = 0.f;
#pragma unroll
            for (int q = 0; q < 4; q++) { float d = o[q] - mean; vs += d * d; }
#pragma unroll
            for (int off = 16; off; off >>= 1) vs += __shfl_xor_sync(0xffffffffu, vs, off);
            float inv = rsqrtf(vs * (1.f / 128.f) + 1e-5f);
            float ssum = 0.f;
#pragma unroll
            for (int q = 0; q < 4; q++)
                ssum += tanhf((o[q] - mean) * inv * gg[q] + bb[q]) * aw[q];
#pragma unroll
            for (int off = 16; off; off >>= 1) ssum += __shfl_xor_sync(0xffffffffu, ssum, off);
            sc[t] = ssum + ab;
            smax = fmaxf(smax, sc[t]);
        }
    }
    float den = 0.f, wts[TT];
#pragma unroll
    for (int t = 0; t < TT; t++) {
        wts[t] = (t < len) ? expf(sc[t] - smax) : 0.f;
        den += wts[t];
    }
    float invden = 1.f / den;
    float accq[4] = {0.f, 0.f, 0.f, 0.f};
#pragma unroll
    for (int t = 0; t < TT; t++) {
        if (t < len) {
            float wt = wts[t] * invden;
#pragma unroll
            for (int q = 0; q < 4; q++)
                accq[q] += wt * g_lin[((size_t)t * NU + n) * EE + lane + 32 * q];
        }
    }
#pragma unroll
    for (int q = 0; q < 4; q++) {
        __nv_bfloat16 h = __float2bfloat16(accq[q]);
        __nv_bfloat16 l = __float2bfloat16(accq[q] - __bfloat162float(h));
        g_tf_h[(size_t)n * EE + lane + 32 * q] = h;
        g_tf_l[(size_t)n * EE + lane + 32 * q] = l;
    }
}

// ================= host launcher =================
extern "C" void kernel_launch(void* const* d_in, const int* in_sizes, int n_in,
                              void* d_out, int out_size) {
    const int*   units  = (const int*)d_in[0];
    const int*   paths  = (const int*)d_in[1];
    const int*   upd    = (const int*)d_in[2];
    const int*   ppd    = (const int*)d_in[3];
    const float* emb    = (const float*)d_in[4];
    const float* tl_Wif = (const float*)d_in[5];
    const float* tl_Whf = (const float*)d_in[6];
    const float* tl_bf  = (const float*)d_in[7];
    const float* tl_Wib = (const float*)d_in[8];
    const float* tl_Whb = (const float*)d_in[9];
    const float* tl_bb  = (const float*)d_in[10];
    const float* lin_W  = (const float*)d_in[11];
    const float* lin_b  = (const float*)d_in[12];
    const float* ln_g   = (const float*)d_in[13];
    const float* ln_bv  = (const float*)d_in[14];
    const float* attn_w = (const float*)d_in[15];
    const float* attn_b = (const float*)d_in[16];
    const float* pl_Wif = (const float*)d_in[17];
    const float* pl_Whf = (const float*)d_in[18];
    const float* pl_bf  = (const float*)d_in[19];
    const float* pl_Wib = (const float*)d_in[20];
    const float* pl_Whb = (const float*)d_in[21];
    const float* pl_bb  = (const float*)d_in[22];
    const float* ul_W   = (const float*)d_in[23];
    const float* ul_b   = (const float*)d_in[24];
    float* out = (float*)d_out;

    void *pVTf, *pVTb, *pPTf, *pPTb, *pLin, *pZero;
    cudaGetSymbolAddress(&pVTf, g_VTf);    cudaGetSymbolAddress(&pVTb, g_VTb);
    cudaGetSymbolAddress(&pPTf, g_PTf);    cudaGetSymbolAddress(&pPTb, g_PTb);
    cudaGetSymbolAddress(&pLin, g_lin);    cudaGetSymbolAddress(&pZero, g_zero);
    void *pEh, *pEl, *pHch, *pHcl, *pTfh, *pTfl, *pHph, *pHpl, *pWih, *pWil, *pW2h, *pW2l;
    cudaGetSymbolAddress(&pEh, g_emb_h);   cudaGetSymbolAddress(&pEl, g_emb_l);
    cudaGetSymbolAddress(&pHch, g_Hcat_h); cudaGetSymbolAddress(&pHcl, g_Hcat_l);
    cudaGetSymbolAddress(&pTfh, g_tf_h);   cudaGetSymbolAddress(&pTfl, g_tf_l);
    cudaGetSymbolAddress(&pHph, g_Hp_h);   cudaGetSymbolAddress(&pHpl, g_Hp_l);
    cudaGetSymbolAddress(&pWih, g_Wih);    cudaGetSymbolAddress(&pWil, g_Wil);
    cudaGetSymbolAddress(&pW2h, g_W2h);    cudaGetSymbolAddress(&pW2l, g_W2l);
    __nv_bfloat16* Wih = (__nv_bfloat16*)pWih;  __nv_bfloat16* Wil = (__nv_bfloat16*)pWil;
    __nv_bfloat16* W2h = (__nv_bfloat16*)pW2h;  __nv_bfloat16* W2l = (__nv_bfloat16*)pW2l;

    const int MM_SMEM = 4 * 128 * 72 * 2;   // 73728
    cudaFuncSetAttribute(k_mm2<128>, cudaFuncAttributeMaxDynamicSharedMemorySize, MM_SMEM);
    cudaFuncSetAttribute(k_mm2<256>, cudaFuncAttributeMaxDynamicSharedMemorySize, MM_SMEM);
    cudaFuncSetAttribute((const void*)k_lstm<0, TT, NU, 64, 512>,
                         cudaFuncAttributeMaxDynamicSharedMemorySize, 70000);
    cudaFuncSetAttribute((const void*)k_lstm<1, LPATH, NPATH, 16, 256>,
                         cudaFuncAttributeMaxDynamicSharedMemorySize, 70000);
    const int LSTM_SMEM_T = 64 * HH * 4 + 16 * G4 * 4 + G4 * 4 + 4 * 64 * 4;
    const int LSTM_SMEM_P = 16 * HH * 4 + 16 * G4 * 4 + G4 * 4 + 4 * 16 * 4;

    // setup
    k_tok_len<<<NU / 256, 256>>>(units);
    k_transpose4<<<dim3((G4 * HH + 255) / 256, 4), 256>>>(tl_Whf, tl_Whb, pl_Whf, pl_Whb);
    k_plen<<<NPATH / 256, 256>>>(paths, upd, ppd);

    // weight + emb hi/lo conversions
    k_hilo<<<(G4 * EE / 4 + 255) / 256, 256>>>(tl_Wif, Wih + 0 * G4 * EE, Wil + 0 * G4 * EE, G4 * EE / 4);
    k_hilo<<<(G4 * EE / 4 + 255) / 256, 256>>>(tl_Wib, Wih + 1 * G4 * EE, Wil + 1 * G4 * EE, G4 * EE / 4);
    k_hilo<<<(G4 * EE / 4 + 255) / 256, 256>>>(pl_Wif, Wih + 2 * G4 * EE, Wil + 2 * G4 * EE, G4 * EE / 4);
    k_hilo<<<(G4 * EE / 4 + 255) / 256, 256>>>(pl_Wib, Wih + 3 * G4 * EE, Wil + 3 * G4 * EE, G4 * EE / 4);
    k_hilo<<<(EE * 256 / 4 + 255) / 256, 256>>>(lin_W, W2h + 0, W2l + 0, EE * 256 / 4);
    k_hilo<<<(EE * 256 / 4 + 255) / 256, 256>>>(ul_W, W2h + EE * 256, W2l + EE * 256, EE * 256 / 4);
    k_hilo<<<(VOCAB * EE / 4 + 255) / 256, 256>>>(emb, (__nv_bfloat16*)pEh, (__nv_bfloat16*)pEl, VOCAB * EE / 4);

    // VT = emb @ Wi^T + b  (16384 x 512, K=128)
    k_mm2<128><<<dim3(4, VOCAB / 128), 256, MM_SMEM>>>((const __nv_bfloat16*)pEh, (const __nv_bfloat16*)pEl,
        Wih + 0 * G4 * EE, Wil + 0 * G4 * EE, tl_bf, (float*)pVTf, G4);
    k_mm2<128><<<dim3(4, VOCAB / 128), 256, MM_SMEM>>>((const __nv_bfloat16*)pEh, (const __nv_bfloat16*)pEl,
        Wih + 1 * G4 * EE, Wil + 1 * G4 * EE, tl_bb, (float*)pVTb, G4);

    // token BiLSTM -> Hcat hi/lo
    k_lstm<0, TT, NU, 64, 512><<<dim3(NU / 64, 2), 512, LSTM_SMEM_T>>>(
        units, (const float*)pVTf, (const float*)pVTb, nullptr, nullptr,
        (__nv_bfloat16*)pHch, (__nv_bfloat16*)pHcl);

    // lin = Hcat @ lin_W^T + lin_b  (65536 x 128, K=256)
    k_mm2<256><<<dim3(1, TT * NU / 128), 256, MM_SMEM>>>((const __nv_bfloat16*)pHch, (const __nv_bfloat16*)pHcl,
        W2h + 0, W2l + 0, lin_b, (float*)pLin, EE);

    // attention -> tf hi/lo
    k_attn<<<(NU * 32) / 256, 256>>>(ln_g, ln_bv, attn_w, attn_b);

    // PT = tokfeat @ pl_Wi^T  (4096 x 512, K=128)
    k_mm2<128><<<dim3(4, NU / 128), 256, MM_SMEM>>>((const __nv_bfloat16*)pTfh, (const __nv_bfloat16*)pTfl,
        Wih + 2 * G4 * EE, Wil + 2 * G4 * EE, (const float*)pZero, (float*)pPTf, G4);
    k_mm2<128><<<dim3(4, NU / 128), 256, MM_SMEM>>>((const __nv_bfloat16*)pTfh, (const __nv_bfloat16*)pTfl,
        Wih + 3 * G4 * EE, Wil + 3 * G4 * EE, (const float*)pZero, (float*)pPTb, G4);

    // path BiLSTM -> Hp hi/lo
    k_lstm<1, LPATH, NPATH, 16, 256><<<dim3(NPATH / 16, 2), 256, LSTM_SMEM_P>>>(
        paths, (const float*)pPTf, (const float*)pPTb, pl_bf, pl_bb,
        (__nv_bfloat16*)pHph, (__nv_bfloat16*)pHpl);

    // out = Hp @ ul_W^T + ul_b  (32768 x 128, K=256)
    k_mm2<256><<<dim3(1, LPATH * NPATH / 128), 256, MM_SMEM>>>((const __nv_bfloat16*)pHph, (const __nv_bfloat16*)pHpl,
        W2h + EE * 256, W2l + EE * 256, ul_b, out, EE);
}

// round 7
// speedup vs baseline: 1.1883x; 1.1457x over previous
#include <cuda_runtime.h>
#include <cuda_bf16.h>
#include <cstdint>

#define TT 16
#define NU 4096
#define EE 128
#define HH 128
#define G4 512
#define LPATH 32
#define NPATH 1024
#define NB 8
#define VOCAB 16384

typedef unsigned long long u64;

// ================= warp-MMA helpers (non-arch-suffixed PTX, sm_80+) =================
__device__ __forceinline__ uint32_t smem_to_u32(const void* p) {
    uint32_t a;
    asm("{ .reg .u64 t; cvta.to.shared.u64 t, %1; cvt.u32.u64 %0, t; }" : "=r"(a) : "l"(p));
    return a;
}
#define LDSM_X4(r, addr) \
    asm volatile("ldmatrix.sync.aligned.m8n8.x4.shared.b16 {%0,%1,%2,%3}, [%4];" \
        : "=r"((r)[0]), "=r"((r)[1]), "=r"((r)[2]), "=r"((r)[3]) : "r"(addr))

__device__ __forceinline__ void mma16816(float* c, const uint32_t* a, uint32_t b0, uint32_t b1) {
    asm volatile("mma.sync.aligned.m16n8k16.row.col.f32.bf16.bf16.f32 "
        "{%0,%1,%2,%3}, {%4,%5,%6,%7}, {%8,%9}, {%0,%1,%2,%3};"
        : "+f"(c[0]), "+f"(c[1]), "+f"(c[2]), "+f"(c[3])
        : "r"(a[0]), "r"(a[1]), "r"(a[2]), "r"(a[3]), "r"(b0), "r"(b1));
}

// ================= f32x2 packed-FMA helpers (base sm_100 family PTX) =================
__device__ __forceinline__ void ffma2(u64& d, u64 a, u64 b) {
    asm("fma.rn.f32x2 %0, %1, %2, %0;" : "+l"(d) : "l"(a), "l"(b));
}
__device__ __forceinline__ u64 dup2(float x) {
    u64 r; asm("mov.b64 %0, {%1, %1};" : "=l"(r) : "f"(x)); return r;
}
__device__ __forceinline__ float2 unpack2(u64 v) {
    float2 f; asm("mov.b64 {%0, %1}, %2;" : "=f"(f.x), "=f"(f.y) : "l"(v)); return f;
}

// ================= device scratch =================
__device__ int   g_tok_len[NU];
__device__ int   g_p_len[NPATH], g_p_fe[NPATH], g_p_off[NPATH], g_p_un[NPATH];
__device__ float g_VTf[VOCAB * G4], g_VTb[VOCAB * G4];
__device__ float g_PTf[NU * G4],    g_PTb[NU * G4];
__device__ float g_lin[TT * NU * EE];
__device__ float g_WhT[4][HH * G4];
__device__ float g_zero[G4];

__device__ __nv_bfloat16 g_emb_h[VOCAB * EE],  g_emb_l[VOCAB * EE];
__device__ __nv_bfloat16 g_Hcat_h[TT * NU * 2 * HH], g_Hcat_l[TT * NU * 2 * HH];
__device__ __nv_bfloat16 g_tf_h[NU * EE], g_tf_l[NU * EE];
__device__ __nv_bfloat16 g_Hp_h[LPATH * NPATH * 2 * HH], g_Hp_l[LPATH * NPATH * 2 * HH];
__device__ __nv_bfloat16 g_Wih[4][G4 * EE], g_Wil[4][G4 * EE];
__device__ __nv_bfloat16 g_W2h[2][EE * 2 * HH], g_W2l[2][EE * 2 * HH];

// ================= setup kernels =================
__global__ void k_tok_len(const int* __restrict__ units) {
    int n = blockIdx.x * blockDim.x + threadIdx.x;
    if (n >= NU) return;
    int len = TT;
    for (int t = 0; t < TT; t++) if (units[t * NU + n] == 0) { len = t; break; }
    g_tok_len[n] = len;
}

__global__ void k_transpose4(const float* __restrict__ W0, const float* __restrict__ W1,
                             const float* __restrict__ W2, const float* __restrict__ W3) {
    int w = blockIdx.y;
    const float* W = (w == 0) ? W0 : (w == 1) ? W1 : (w == 2) ? W2 : W3;
    int idx = blockIdx.x * blockDim.x + threadIdx.x;
    if (idx >= G4 * HH) return;
    int j = idx >> 7, k = idx & 127;
    g_WhT[w][k * G4 + j] = W[idx];
}

__global__ void k_plen(const int* __restrict__ paths,
                       const int* __restrict__ upd, const int* __restrict__ ppd) {
    int p = blockIdx.x * blockDim.x + threadIdx.x;
    if (p >= NPATH) return;
    int dd = NB - 1, cum = 0;
    for (int i = 0; i < NB; i++) { int nx = cum + ppd[i]; if (p >= cum && p < nx) { dd = i; break; } cum = nx; }
    int off = 0;
    for (int i = 0; i < dd; i++) off += upd[i];
    int un = upd[dd];
    int fe = LPATH;
    for (int t = 0; t < LPATH; t++) if (paths[t * NPATH + p] == -1) { fe = t; break; }
    int plen = LPATH;
    for (int t = 0; t < LPATH; t++) {
        bool msk;
        if (t >= fe) msk = true;
        else { int v = paths[t * NPATH + p]; msk = (v < 0) || (v > un); }
        if (msk) { plen = t; break; }
    }
    g_p_len[p] = plen; g_p_fe[p] = fe; g_p_off[p] = off; g_p_un[p] = un;
}

__global__ void k_hilo(const float* __restrict__ src, __nv_bfloat16* __restrict__ hi,
                       __nv_bfloat16* __restrict__ lo, int n4) {
    int i = blockIdx.x * blockDim.x + threadIdx.x;
    if (i >= n4) return;
    float4 v = reinterpret_cast<const float4*>(src)[i];
    __nv_bfloat16 h0 = __float2bfloat16(v.x), h1 = __float2bfloat16(v.y);
    __nv_bfloat16 h2 = __float2bfloat16(v.z), h3 = __float2bfloat16(v.w);
    __nv_bfloat16 l0 = __float2bfloat16(v.x - __bfloat162float(h0));
    __nv_bfloat16 l1 = __float2bfloat16(v.y - __bfloat162float(h1));
    __nv_bfloat16 l2 = __float2bfloat16(v.z - __bfloat162float(h2));
    __nv_bfloat16 l3 = __float2bfloat16(v.w - __bfloat162float(h3));
    __nv_bfloat162* H = reinterpret_cast<__nv_bfloat162*>(hi);
    __nv_bfloat162* L = reinterpret_cast<__nv_bfloat162*>(lo);
    H[2 * i] = __nv_bfloat162(h0, h1); H[2 * i + 1] = __nv_bfloat162(h2, h3);
    L[2 * i] = __nv_bfloat162(l0, l1); L[2 * i + 1] = __nv_bfloat162(l2, l3);
}

// ================= warp-MMA split-bf16 GEMM (unchanged from R6, passing) =================
template <int K>
__global__ __launch_bounds__(256) void k_mm2(
    const __nv_bfloat16* __restrict__ Ah, const __nv_bfloat16* __restrict__ Al,
    const __nv_bfloat16* __restrict__ Bh, const __nv_bfloat16* __restrict__ Bl,
    const float* __restrict__ bias, float* __restrict__ C, int Ntot)
{
    constexpr int LDS = 72;
    extern __shared__ __nv_bfloat16 sm[];
    __nv_bfloat16* sAh = sm;
    __nv_bfloat16* sAl = sAh + 128 * LDS;
    __nv_bfloat16* sBh = sAl + 128 * LDS;
    __nv_bfloat16* sBl = sBh + 128 * LDS;

    const int tid = threadIdx.x, lane = tid & 31, wid = tid >> 5;
    const int m0 = blockIdx.y * 128, n0 = blockIdx.x * 128;
    const int wm = (wid & 3) * 32, wn = (wid >> 2) * 64;
    const int g = lane >> 2, tg = lane & 3;
    const int seg = lane >> 3, i8 = lane & 7;

    const uint32_t sAh_b = smem_to_u32(sAh), sAl_b = smem_to_u32(sAl);
    const uint32_t sBh_b = smem_to_u32(sBh), sBl_b = smem_to_u32(sBl);

    float acc[2][8][4];
#pragma unroll
    for (int im = 0; im < 2; im++)
#pragma unroll
        for (int jn = 0; jn < 8; jn++)
#pragma unroll
            for (int q = 0; q < 4; q++) acc[im][jn][q] = 0.f;

    for (int kc = 0; kc < K; kc += 64) {
        if (kc) __syncthreads();
        {
            const __nv_bfloat16* srcs[4] = {Ah, Al, Bh, Bl};
            __nv_bfloat16* dsts[4] = {sAh, sAl, sBh, sBl};
            const int r0s[4] = {m0, m0, n0, n0};
#pragma unroll
            for (int t = 0; t < 4; t++) {
                for (int v = tid; v < 1024; v += 256) {
                    int row = v >> 3, q = (v & 7) * 8;
                    *reinterpret_cast<uint4*>(dsts[t] + row * LDS + q) =
                        *reinterpret_cast<const uint4*>(srcs[t] + (size_t)(r0s[t] + row) * K + kc + q);
                }
            }
        }
        __syncthreads();

#pragma unroll
        for (int ks = 0; ks < 4; ks++) {
            const int k0 = ks * 16;
            uint32_t ah[2][4], al[2][4];
#pragma unroll
            for (int im = 0; im < 2; im++) {
                int arow = wm + im * 16 + (seg & 1) * 8 + i8;
                int acol = k0 + (seg >> 1) * 8;
                LDSM_X4(ah[im], sAh_b + (uint32_t)(arow * LDS + acol) * 2u);
                LDSM_X4(al[im], sAl_b + (uint32_t)(arow * LDS + acol) * 2u);
            }
#pragma unroll
            for (int ip = 0; ip < 4; ip++) {
                int brow = wn + ip * 16 + (seg >> 1) * 8 + i8;
                int bcol = k0 + (seg & 1) * 8;
                uint32_t bh4[4], bl4[4];
                LDSM_X4(bh4, sBh_b + (uint32_t)(brow * LDS + bcol) * 2u);
                LDSM_X4(bl4, sBl_b + (uint32_t)(brow * LDS + bcol) * 2u);
#pragma unroll
                for (int im = 0; im < 2; im++) {
#pragma unroll
                    for (int hf = 0; hf < 2; hf++) {
                        float* c = acc[im][ip * 2 + hf];
                        mma16816(c, ah[im], bh4[2 * hf], bh4[2 * hf + 1]);
                        mma16816(c, al[im], bh4[2 * hf], bh4[2 * hf + 1]);
                        mma16816(c, ah[im], bl4[2 * hf], bl4[2 * hf + 1]);
                    }
                }
            }
        }
    }

#pragma unroll
    for (int im = 0; im < 2; im++) {
#pragma unroll
        for (int jn = 0; jn < 8; jn++) {
            int col = n0 + wn + jn * 8 + tg * 2;
            float b0v = bias[col], b1v = bias[col + 1];
            int row0 = m0 + wm + im * 16 + g;
            float2 v0 = make_float2(acc[im][jn][0] + b0v, acc[im][jn][1] + b1v);
            float2 v1 = make_float2(acc[im][jn][2] + b0v, acc[im][jn][3] + b1v);
            *reinterpret_cast<float2*>(C + (size_t)row0 * Ntot + col) = v0;
            *reinterpret_cast<float2*>(C + (size_t)(row0 + 8) * Ntot + col) = v1;
        }
    }
}

// ================= persistent BiLSTM: FFMA2 inner loop + double-buffered Wh^T =================
__device__ __forceinline__ float sigm(float x) { return 1.f / (1.f + expf(-x)); }

template <int MODE, int TSTEPS, int NSEQ, int ROWS, int THREADS>
__global__ __launch_bounds__(THREADS) void k_lstm(
    const int* __restrict__ idxmat,
    const float* __restrict__ tab_f, const float* __restrict__ tab_b,
    const float* __restrict__ bias_f, const float* __restrict__ bias_b,
    __nv_bfloat16* __restrict__ Hh, __nv_bfloat16* __restrict__ Hl)
{
    constexpr int NW = THREADS / 32, RPT = ROWS / NW;
    constexpr int N4 = 2048 / THREADS;          // float4 per thread per chunk prefetch
    extern __shared__ char dsm[];
    float* hs    = reinterpret_cast<float*>(dsm);       // [ROWS][HH]
    float* wst   = hs + ROWS * HH;                      // [2][16*G4]
    float* sbias = wst + 2 * 16 * G4;                   // [G4]
    int* slen = reinterpret_cast<int*>(sbias + G4);
    int* sfe = slen + ROWS; int* soff = sfe + ROWS; int* sun = soff + ROWS;

    const int dir = blockIdx.y;
    const float* __restrict__ tab = dir ? tab_b : tab_f;
    const float* __restrict__ WhT = g_WhT[2 * MODE + dir];
    const int n0 = blockIdx.x * ROWS;
    const int tid = threadIdx.x, jt = tid & 31, rt = tid >> 5;
    const int e0 = jt * 4, r0 = rt * RPT;

    if (MODE == 1) {
        const float* b = dir ? bias_b : bias_f;
        for (int i = tid; i < G4; i += THREADS) sbias[i] = b[i];
    }
    float c[RPT][4];
#pragma unroll
    for (int r = 0; r < RPT; r++) {
#pragma unroll
        for (int u = 0; u < 4; u++) c[r][u] = 0.f;
        *reinterpret_cast<float4*>(&hs[(r0 + r) * HH + e0]) = make_float4(0.f, 0.f, 0.f, 0.f);
    }
    if (tid < ROWS) {
        int n = n0 + tid;
        slen[tid] = MODE ? g_p_len[n] : g_tok_len[n];
        if (MODE) { sfe[tid] = g_p_fe[n]; soff[tid] = g_p_off[n]; sun[tid] = g_p_un[n]; }
    }
    // preload chunk 0 into buffer 0
#pragma unroll
    for (int t = 0; t < N4; t++) {
        int i = tid + t * THREADS;
        reinterpret_cast<float4*>(wst)[i] = reinterpret_cast<const float4*>(WhT)[i];
    }
    __syncthreads();

    for (int s = 0; s < TSTEPS; s++) {
        u64 acc64[RPT][8];
#pragma unroll
        for (int r = 0; r < RPT; r++)
#pragma unroll
            for (int j = 0; j < 8; j++) acc64[r][j] = 0ull;

#pragma unroll
        for (int ch = 0; ch < 8; ch++) {
            const float* wcur = wst + (ch & 1) * (16 * G4);
            float* wnxt = wst + ((ch + 1) & 1) * (16 * G4);
            const int nxt = (ch + 1) & 7;
            // issue prefetch LDGs for next chunk (same weights every step; buffers rotate)
            float4 pre[N4];
#pragma unroll
            for (int t = 0; t < N4; t++)
                pre[t] = reinterpret_cast<const float4*>(WhT)[nxt * 2048 + tid + t * THREADS];

#pragma unroll
            for (int kk = 0; kk < 16; kk++) {
                ulonglong2 wA = *reinterpret_cast<const ulonglong2*>(&wcur[kk * G4 + e0]);
                ulonglong2 wB = *reinterpret_cast<const ulonglong2*>(&wcur[kk * G4 + 128 + e0]);
                ulonglong2 wC = *reinterpret_cast<const ulonglong2*>(&wcur[kk * G4 + 256 + e0]);
                ulonglong2 wD = *reinterpret_cast<const ulonglong2*>(&wcur[kk * G4 + 384 + e0]);
#pragma unroll
                for (int r = 0; r < RPT; r++) {
                    u64 h2 = dup2(hs[(r0 + r) * HH + ch * 16 + kk]);
                    ffma2(acc64[r][0], h2, wA.x); ffma2(acc64[r][1], h2, wA.y);
                    ffma2(acc64[r][2], h2, wB.x); ffma2(acc64[r][3], h2, wB.y);
                    ffma2(acc64[r][4], h2, wC.x); ffma2(acc64[r][5], h2, wC.y);
                    ffma2(acc64[r][6], h2, wD.x); ffma2(acc64[r][7], h2, wD.y);
                }
            }
            // store prefetched chunk into the other buffer
#pragma unroll
            for (int t = 0; t < N4; t++)
                reinterpret_cast<float4*>(wnxt)[tid + t * THREADS] = pre[t];
            __syncthreads();
        }

        float hnew[RPT][4];
#pragma unroll
        for (int r = 0; r < RPT; r++) {
            // unpack accumulators: j pairs -> 16 gate values
            float a16[16];
#pragma unroll
            for (int j = 0; j < 8; j++) {
                float2 v = unpack2(acc64[r][j]);
                a16[j * 2] = v.x; a16[j * 2 + 1] = v.y;
            }
            int rr = r0 + r, n = n0 + rr, len = slen[rr];
            int gi = dir ? min(max(len - 1 - s, 0), TSTEPS - 1) : s;
            float gv[16];
            if (MODE == 0) {
                int id = idxmat[(size_t)gi * NSEQ + n];
                const float* grow = tab + (size_t)id * G4;
                float4 a0 = *reinterpret_cast<const float4*>(&grow[e0]);
                float4 a1 = *reinterpret_cast<const float4*>(&grow[128 + e0]);
                float4 a2 = *reinterpret_cast<const float4*>(&grow[256 + e0]);
                float4 a3 = *reinterpret_cast<const float4*>(&grow[384 + e0]);
                gv[0]=a0.x; gv[1]=a0.y; gv[2]=a0.z; gv[3]=a0.w;
                gv[4]=a1.x; gv[5]=a1.y; gv[6]=a1.z; gv[7]=a1.w;
                gv[8]=a2.x; gv[9]=a2.y; gv[10]=a2.z; gv[11]=a2.w;
                gv[12]=a3.x; gv[13]=a3.y; gv[14]=a3.z; gv[15]=a3.w;
            } else {
                int pl = idxmat[(size_t)gi * NSEQ + n];
                bool keep = (gi < sfe[rr]) && (pl >= 0) && (pl < sun[rr]);
                float4 b0 = *reinterpret_cast<const float4*>(&sbias[e0]);
                float4 b1 = *reinterpret_cast<const float4*>(&sbias[128 + e0]);
                float4 b2 = *reinterpret_cast<const float4*>(&sbias[256 + e0]);
                float4 b3 = *reinterpret_cast<const float4*>(&sbias[384 + e0]);
                gv[0]=b0.x; gv[1]=b0.y; gv[2]=b0.z; gv[3]=b0.w;
                gv[4]=b1.x; gv[5]=b1.y; gv[6]=b1.z; gv[7]=b1.w;
                gv[8]=b2.x; gv[9]=b2.y; gv[10]=b2.z; gv[11]=b2.w;
                gv[12]=b3.x; gv[13]=b3.y; gv[14]=b3.z; gv[15]=b3.w;
                if (keep) {
                    int gidx = min(pl + soff[rr], NU - 1);
                    const float* grow = tab + (size_t)gidx * G4;
                    float4 t0 = *reinterpret_cast<const float4*>(&grow[e0]);
                    float4 t1 = *reinterpret_cast<const float4*>(&grow[128 + e0]);
                    float4 t2 = *reinterpret_cast<const float4*>(&grow[256 + e0]);
                    float4 t3 = *reinterpret_cast<const float4*>(&grow[384 + e0]);
                    gv[0]+=t0.x; gv[1]+=t0.y; gv[2]+=t0.z; gv[3]+=t0.w;
                    gv[4]+=t1.x; gv[5]+=t1.y; gv[6]+=t1.z; gv[7]+=t1.w;
                    gv[8]+=t2.x; gv[9]+=t2.y; gv[10]+=t2.z; gv[11]+=t2.w;
                    gv[12]+=t3.x; gv[13]+=t3.y; gv[14]+=t3.z; gv[15]+=t3.w;
                }
            }
#pragma unroll
            for (int u = 0; u < 4; u++) {
                float iv = a16[u]      + gv[u];
                float fv = a16[4 + u]  + gv[4 + u];
                float gg = a16[8 + u]  + gv[8 + u];
                float ov = a16[12 + u] + gv[12 + u];
                float cn = sigm(fv) * c[r][u] + sigm(iv) * tanhf(gg);
                c[r][u] = cn;
                hnew[r][u] = sigm(ov) * tanhf(cn);
            }
            if (s < len) {
                int wi = dir ? (len - 1 - s) : s;
                size_t base = ((size_t)wi * NSEQ + n) * (2 * HH) + dir * HH + e0;
                __nv_bfloat16 hb[4], lb[4];
#pragma unroll
                for (int u = 0; u < 4; u++) {
                    hb[u] = __float2bfloat16(hnew[r][u]);
                    lb[u] = __float2bfloat16(hnew[r][u] - __bfloat162float(hb[u]));
                }
                *reinterpret_cast<uint2*>(Hh + base) = *reinterpret_cast<uint2*>(hb);
                *reinterpret_cast<uint2*>(Hl + base) = *reinterpret_cast<uint2*>(lb);
            } else if (dir == 0) {
                uint2 z = make_uint2(0u, 0u);
                size_t b0 = ((size_t)s * NSEQ + n) * (2 * HH) + e0;
                *reinterpret_cast<uint2*>(Hh + b0) = z;
                *reinterpret_cast<uint2*>(Hl + b0) = z;
                *reinterpret_cast<uint2*>(Hh + b0 + HH) = z;
                *reinterpret_cast<uint2*>(Hl + b0 + HH) = z;
            }
        }
        __syncthreads();
#pragma unroll
        for (int r = 0; r < RPT; r++)
            *reinterpret_cast<float4*>(&hs[(r0 + r) * HH + e0]) =
                make_float4(hnew[r][0], hnew[r][1], hnew[r][2], hnew[r][3]);
        __syncthreads();
    }
}

// ================= attention pooling (writes tf hi/lo) =================
__global__ void k_attn(const float* __restrict__ ln_g, const float* __restrict__ ln_b,
                       const float* __restrict__ attn_w, const float* __restrict__ attn_bp) {
    int gwarp = (blockIdx.x * blockDim.x + threadIdx.x) >> 5;
    int lane = threadIdx.x & 31;
    if (gwarp >= NU) return;
    int n = gwarp, len = g_tok_len[n];

    float gg[4], bb[4], aw[4];
#pragma unroll
    for (int q = 0; q < 4; q++) {
        int e = lane + 32 * q;
        gg[q] = ln_g[e]; bb[q] = ln_b[e]; aw[q] = attn_w[e];
    }
    float ab = attn_bp[0];

    float sc[TT], smax = -1e30f;
#pragma unroll
    for (int t = 0; t < TT; t++) {
        sc[t] = -1e30f;
        if (t < len) {
            float o[4], lsum = 0.f;
#pragma unroll
            for (int q = 0; q < 4; q++) {
                o[q] = g_lin[((size_t)t * NU + n) * EE + lane + 32 * q];
                lsum += o[q];
            }
#pragma unroll
            for (int off = 16; off; off >>= 1) lsum += __shfl_xor_sync(0xffffffffu, lsum, off);
            float mean = lsum * (1.f / 128.f);
            float vs = 0.f;
#pragma unroll
            for (int q = 0; q < 4; q++) { float d = o[q] - mean; vs += d * d; }
#pragma unroll
            for (int off = 16; off; off >>= 1) vs += __shfl_xor_sync(0xffffffffu, vs, off);
            float inv = rsqrtf(vs * (1.f / 128.f) + 1e-5f);
            float ssum = 0.f;
#pragma unroll
            for (int q = 0; q < 4; q++)
                ssum += tanhf((o[q] - mean) * inv * gg[q] + bb[q]) * aw[q];
#pragma unroll
            for (int off = 16; off; off >>= 1) ssum += __shfl_xor_sync(0xffffffffu, ssum, off);
            sc[t] = ssum + ab;
            smax = fmaxf(smax, sc[t]);
        }
    }
    float den = 0.f, wts[TT];
#pragma unroll
    for (int t = 0; t < TT; t++) {
        wts[t] = (t < len) ? expf(sc[t] - smax) : 0.f;
        den += wts[t];
    }
    float invden = 1.f / den;
    float accq[4] = {0.f, 0.f, 0.f, 0.f};
#pragma unroll
    for (int t = 0; t < TT; t++) {
        if (t < len) {
            float wt = wts[t] * invden;
#pragma unroll
            for (int q = 0; q < 4; q++)
                accq[q] += wt * g_lin[((size_t)t * NU + n) * EE + lane + 32 * q];
        }
    }
#pragma unroll
    for (int q = 0; q < 4; q++) {
        __nv_bfloat16 h = __float2bfloat16(accq[q]);
        __nv_bfloat16 l = __float2bfloat16(accq[q] - __bfloat162float(h));
        g_tf_h[(size_t)n * EE + lane + 32 * q] = h;
        g_tf_l[(size_t)n * EE + lane + 32 * q] = l;
    }
}

// ================= host launcher =================
extern "C" void kernel_launch(void* const* d_in, const int* in_sizes, int n_in,
                              void* d_out, int out_size) {
    const int*   units  = (const int*)d_in[0];
    const int*   paths  = (const int*)d_in[1];
    const int*   upd    = (const int*)d_in[2];
    const int*   ppd    = (const int*)d_in[3];
    const float* emb    = (const float*)d_in[4];
    const float* tl_Wif = (const float*)d_in[5];
    const float* tl_Whf = (const float*)d_in[6];
    const float* tl_bf  = (const float*)d_in[7];
    const float* tl_Wib = (const float*)d_in[8];
    const float* tl_Whb = (const float*)d_in[9];
    const float* tl_bb  = (const float*)d_in[10];
    const float* lin_W  = (const float*)d_in[11];
    const float* lin_b  = (const float*)d_in[12];
    const float* ln_g   = (const float*)d_in[13];
    const float* ln_bv  = (const float*)d_in[14];
    const float* attn_w = (const float*)d_in[15];
    const float* attn_b = (const float*)d_in[16];
    const float* pl_Wif = (const float*)d_in[17];
    const float* pl_Whf = (const float*)d_in[18];
    const float* pl_bf  = (const float*)d_in[19];
    const float* pl_Wib = (const float*)d_in[20];
    const float* pl_Whb = (const float*)d_in[21];
    const float* pl_bb  = (const float*)d_in[22];
    const float* ul_W   = (const float*)d_in[23];
    const float* ul_b   = (const float*)d_in[24];
    float* out = (float*)d_out;

    void *pVTf, *pVTb, *pPTf, *pPTb, *pLin, *pZero;
    cudaGetSymbolAddress(&pVTf, g_VTf);    cudaGetSymbolAddress(&pVTb, g_VTb);
    cudaGetSymbolAddress(&pPTf, g_PTf);    cudaGetSymbolAddress(&pPTb, g_PTb);
    cudaGetSymbolAddress(&pLin, g_lin);    cudaGetSymbolAddress(&pZero, g_zero);
    void *pEh, *pEl, *pHch, *pHcl, *pTfh, *pTfl, *pHph, *pHpl, *pWih, *pWil, *pW2h, *pW2l;
    cudaGetSymbolAddress(&pEh, g_emb_h);   cudaGetSymbolAddress(&pEl, g_emb_l);
    cudaGetSymbolAddress(&pHch, g_Hcat_h); cudaGetSymbolAddress(&pHcl, g_Hcat_l);
    cudaGetSymbolAddress(&pTfh, g_tf_h);   cudaGetSymbolAddress(&pTfl, g_tf_l);
    cudaGetSymbolAddress(&pHph, g_Hp_h);   cudaGetSymbolAddress(&pHpl, g_Hp_l);
    cudaGetSymbolAddress(&pWih, g_Wih);    cudaGetSymbolAddress(&pWil, g_Wil);
    cudaGetSymbolAddress(&pW2h, g_W2h);    cudaGetSymbolAddress(&pW2l, g_W2l);
    __nv_bfloat16* Wih = (__nv_bfloat16*)pWih;  __nv_bfloat16* Wil = (__nv_bfloat16*)pWil;
    __nv_bfloat16* W2h = (__nv_bfloat16*)pW2h;  __nv_bfloat16* W2l = (__nv_bfloat16*)pW2l;

    const int MM_SMEM = 4 * 128 * 72 * 2;   // 73728
    const int LSTM_SMEM_T = 64 * HH * 4 + 2 * 16 * G4 * 4 + G4 * 4 + 4 * 64 * 4;   // ~101.4KB
    const int LSTM_SMEM_P = 16 * HH * 4 + 2 * 16 * G4 * 4 + G4 * 4 + 4 * 16 * 4;   // ~76KB
    cudaFuncSetAttribute(k_mm2<128>, cudaFuncAttributeMaxDynamicSharedMemorySize, MM_SMEM);
    cudaFuncSetAttribute(k_mm2<256>, cudaFuncAttributeMaxDynamicSharedMemorySize, MM_SMEM);
    cudaFuncSetAttribute((const void*)k_lstm<0, TT, NU, 64, 512>,
                         cudaFuncAttributeMaxDynamicSharedMemorySize, LSTM_SMEM_T + 1024);
    cudaFuncSetAttribute((const void*)k_lstm<1, LPATH, NPATH, 16, 256>,
                         cudaFuncAttributeMaxDynamicSharedMemorySize, LSTM_SMEM_P + 1024);

    // setup
    k_tok_len<<<NU / 256, 256>>>(units);
    k_transpose4<<<dim3((G4 * HH + 255) / 256, 4), 256>>>(tl_Whf, tl_Whb, pl_Whf, pl_Whb);
    k_plen<<<NPATH / 256, 256>>>(paths, upd, ppd);

    // weight + emb hi/lo conversions
    k_hilo<<<(G4 * EE / 4 + 255) / 256, 256>>>(tl_Wif, Wih + 0 * G4 * EE, Wil + 0 * G4 * EE, G4 * EE / 4);
    k_hilo<<<(G4 * EE / 4 + 255) / 256, 256>>>(tl_Wib, Wih + 1 * G4 * EE, Wil + 1 * G4 * EE, G4 * EE / 4);
    k_hilo<<<(G4 * EE / 4 + 255) / 256, 256>>>(pl_Wif, Wih + 2 * G4 * EE, Wil + 2 * G4 * EE, G4 * EE / 4);
    k_hilo<<<(G4 * EE / 4 + 255) / 256, 256>>>(pl_Wib, Wih + 3 * G4 * EE, Wil + 3 * G4 * EE, G4 * EE / 4);
    k_hilo<<<(EE * 256 / 4 + 255) / 256, 256>>>(lin_W, W2h + 0, W2l + 0, EE * 256 / 4);
    k_hilo<<<(EE * 256 / 4 + 255) / 256, 256>>>(ul_W, W2h + EE * 256, W2l + EE * 256, EE * 256 / 4);
    k_hilo<<<(VOCAB * EE / 4 + 255) / 256, 256>>>(emb, (__nv_bfloat16*)pEh, (__nv_bfloat16*)pEl, VOCAB * EE / 4);

    // VT = emb @ Wi^T + b  (16384 x 512, K=128)
    k_mm2<128><<<dim3(4, VOCAB / 128), 256, MM_SMEM>>>((const __nv_bfloat16*)pEh, (const __nv_bfloat16*)pEl,
        Wih + 0 * G4 * EE, Wil + 0 * G4 * EE, tl_bf, (float*)pVTf, G4);
    k_mm2<128><<<dim3(4, VOCAB / 128), 256, MM_SMEM>>>((const __nv_bfloat16*)pEh, (const __nv_bfloat16*)pEl,
        Wih + 1 * G4 * EE, Wil + 1 * G4 * EE, tl_bb, (float*)pVTb, G4);

    // token BiLSTM -> Hcat hi/lo
    k_lstm<0, TT, NU, 64, 512><<<dim3(NU / 64, 2), 512, LSTM_SMEM_T>>>(
        units, (const float*)pVTf, (const float*)pVTb, nullptr, nullptr,
        (__nv_bfloat16*)pHch, (__nv_bfloat16*)pHcl);

    // lin = Hcat @ lin_W^T + lin_b  (65536 x 128, K=256)
    k_mm2<256><<<dim3(1, TT * NU / 128), 256, MM_SMEM>>>((const __nv_bfloat16*)pHch, (const __nv_bfloat16*)pHcl,
        W2h + 0, W2l + 0, lin_b, (float*)pLin, EE);

    // attention -> tf hi/lo
    k_attn<<<(NU * 32) / 256, 256>>>(ln_g, ln_bv, attn_w, attn_b);

    // PT = tokfeat @ pl_Wi^T  (4096 x 512, K=128)
    k_mm2<128><<<dim3(4, NU / 128), 256, MM_SMEM>>>((const __nv_bfloat16*)pTfh, (const __nv_bfloat16*)pTfl,
        Wih + 2 * G4 * EE, Wil + 2 * G4 * EE, (const float*)pZero, (float*)pPTf, G4);
    k_mm2<128><<<dim3(4, NU / 128), 256, MM_SMEM>>>((const __nv_bfloat16*)pTfh, (const __nv_bfloat16*)pTfl,
        Wih + 3 * G4 * EE, Wil + 3 * G4 * EE, (const float*)pZero, (float*)pPTb, G4);

    // path BiLSTM -> Hp hi/lo
    k_lstm<1, LPATH, NPATH, 16, 256><<<dim3(NPATH / 16, 2), 256, LSTM_SMEM_P>>>(
        paths, (const float*)pPTf, (const float*)pPTb, pl_bf, pl_bb,
        (__nv_bfloat16*)pHph, (__nv_bfloat16*)pHpl);

    // out = Hp @ ul_W^T + ul_b  (32768 x 128, K=256)
    k_mm2<256><<<dim3(1, LPATH * NPATH / 128), 256, MM_SMEM>>>((const __nv_bfloat16*)pHph, (const __nv_bfloat16*)pHpl,
        W2h + EE * 256, W2l + EE * 256, ul_b, out, EE);
}

// round 8
// speedup vs baseline: 1.1902x; 1.0016x over previous
#include <cuda_runtime.h>
#include <cuda_bf16.h>
#include <cstdint>

#define TT 16
#define NU 4096
#define EE 128
#define HH 128
#define G4 512
#define LPATH 32
#define NPATH 1024
#define NB 8
#define VOCAB 16384

typedef unsigned long long u64;

// ================= warp-MMA helpers (non-arch-suffixed PTX, sm_80+) =================
__device__ __forceinline__ uint32_t smem_to_u32(const void* p) {
    uint32_t a;
    asm("{ .reg .u64 t; cvta.to.shared.u64 t, %1; cvt.u32.u64 %0, t; }" : "=r"(a) : "l"(p));
    return a;
}
#define LDSM_X4(r, addr) \
    asm volatile("ldmatrix.sync.aligned.m8n8.x4.shared.b16 {%0,%1,%2,%3}, [%4];" \
        : "=r"((r)[0]), "=r"((r)[1]), "=r"((r)[2]), "=r"((r)[3]) : "r"(addr))

__device__ __forceinline__ void mma16816(float* c, const uint32_t* a, uint32_t b0, uint32_t b1) {
    asm volatile("mma.sync.aligned.m16n8k16.row.col.f32.bf16.bf16.f32 "
        "{%0,%1,%2,%3}, {%4,%5,%6,%7}, {%8,%9}, {%0,%1,%2,%3};"
        : "+f"(c[0]), "+f"(c[1]), "+f"(c[2]), "+f"(c[3])
        : "r"(a[0]), "r"(a[1]), "r"(a[2]), "r"(a[3]), "r"(b0), "r"(b1));
}

// ================= f32x2 packed-FMA helpers (base sm_100 family PTX) =================
__device__ __forceinline__ void ffma2(u64& d, u64 a, u64 b) {
    asm("fma.rn.f32x2 %0, %1, %2, %0;" : "+l"(d) : "l"(a), "l"(b));
}
__device__ __forceinline__ u64 dup2(float x) {
    u64 r; asm("mov.b64 %0, {%1, %1};" : "=l"(r) : "f"(x)); return r;
}
__device__ __forceinline__ float2 unpack2(u64 v) {
    float2 f; asm("mov.b64 {%0, %1}, %2;" : "=f"(f.x), "=f"(f.y) : "l"(v)); return f;
}

// ================= device scratch =================
__device__ int   g_tok_len[NU];
__device__ int   g_p_len[NPATH], g_p_fe[NPATH], g_p_off[NPATH], g_p_un[NPATH];
__device__ float g_VTf[VOCAB * G4], g_VTb[VOCAB * G4];
__device__ float g_PTf[NU * G4],    g_PTb[NU * G4];
__device__ float g_lin[TT * NU * EE];
__device__ float g_WhT[4][HH * G4];
__device__ float g_zero[G4];

__device__ __nv_bfloat16 g_emb_h[VOCAB * EE],  g_emb_l[VOCAB * EE];
__device__ __nv_bfloat16 g_Hcat_h[TT * NU * 2 * HH], g_Hcat_l[TT * NU * 2 * HH];
__device__ __nv_bfloat16 g_tf_h[NU * EE], g_tf_l[NU * EE];
__device__ __nv_bfloat16 g_Hp_h[LPATH * NPATH * 2 * HH], g_Hp_l[LPATH * NPATH * 2 * HH];
__device__ __nv_bfloat16 g_Wih[4][G4 * EE], g_Wil[4][G4 * EE];
__device__ __nv_bfloat16 g_W2h[2][EE * 2 * HH], g_W2l[2][EE * 2 * HH];

// ================= setup kernels =================
__global__ void k_tok_len(const int* __restrict__ units) {
    int n = blockIdx.x * blockDim.x + threadIdx.x;
    if (n >= NU) return;
    int len = TT;
    for (int t = 0; t < TT; t++) if (units[t * NU + n] == 0) { len = t; break; }
    g_tok_len[n] = len;
}

__global__ void k_transpose4(const float* __restrict__ W0, const float* __restrict__ W1,
                             const float* __restrict__ W2, const float* __restrict__ W3) {
    int w = blockIdx.y;
    const float* W = (w == 0) ? W0 : (w == 1) ? W1 : (w == 2) ? W2 : W3;
    int idx = blockIdx.x * blockDim.x + threadIdx.x;
    if (idx >= G4 * HH) return;
    int j = idx >> 7, k = idx & 127;
    g_WhT[w][k * G4 + j] = W[idx];
}

__global__ void k_plen(const int* __restrict__ paths,
                       const int* __restrict__ upd, const int* __restrict__ ppd) {
    int p = blockIdx.x * blockDim.x + threadIdx.x;
    if (p >= NPATH) return;
    int dd = NB - 1, cum = 0;
    for (int i = 0; i < NB; i++) { int nx = cum + ppd[i]; if (p >= cum && p < nx) { dd = i; break; } cum = nx; }
    int off = 0;
    for (int i = 0; i < dd; i++) off += upd[i];
    int un = upd[dd];
    int fe = LPATH;
    for (int t = 0; t < LPATH; t++) if (paths[t * NPATH + p] == -1) { fe = t; break; }
    int plen = LPATH;
    for (int t = 0; t < LPATH; t++) {
        bool msk;
        if (t >= fe) msk = true;
        else { int v = paths[t * NPATH + p]; msk = (v < 0) || (v > un); }
        if (msk) { plen = t; break; }
    }
    g_p_len[p] = plen; g_p_fe[p] = fe; g_p_off[p] = off; g_p_un[p] = un;
}

__global__ void k_hilo(const float* __restrict__ src, __nv_bfloat16* __restrict__ hi,
                       __nv_bfloat16* __restrict__ lo, int n4) {
    int i = blockIdx.x * blockDim.x + threadIdx.x;
    if (i >= n4) return;
    float4 v = reinterpret_cast<const float4*>(src)[i];
    __nv_bfloat16 h0 = __float2bfloat16(v.x), h1 = __float2bfloat16(v.y);
    __nv_bfloat16 h2 = __float2bfloat16(v.z), h3 = __float2bfloat16(v.w);
    __nv_bfloat16 l0 = __float2bfloat16(v.x - __bfloat162float(h0));
    __nv_bfloat16 l1 = __float2bfloat16(v.y - __bfloat162float(h1));
    __nv_bfloat16 l2 = __float2bfloat16(v.z - __bfloat162float(h2));
    __nv_bfloat16 l3 = __float2bfloat16(v.w - __bfloat162float(h3));
    __nv_bfloat162* H = reinterpret_cast<__nv_bfloat162*>(hi);
    __nv_bfloat162* L = reinterpret_cast<__nv_bfloat162*>(lo);
    H[2 * i] = __nv_bfloat162(h0, h1); H[2 * i + 1] = __nv_bfloat162(h2, h3);
    L[2 * i] = __nv_bfloat162(l0, l1); L[2 * i + 1] = __nv_bfloat162(l2, l3);
}

// ================= warp-MMA split-bf16 GEMM (unchanged from R6, passing) =================
template <int K>
__global__ __launch_bounds__(256) void k_mm2(
    const __nv_bfloat16* __restrict__ Ah, const __nv_bfloat16* __restrict__ Al,
    const __nv_bfloat16* __restrict__ Bh, const __nv_bfloat16* __restrict__ Bl,
    const float* __restrict__ bias, float* __restrict__ C, int Ntot)
{
    constexpr int LDS = 72;
    extern __shared__ __nv_bfloat16 sm[];
    __nv_bfloat16* sAh = sm;
    __nv_bfloat16* sAl = sAh + 128 * LDS;
    __nv_bfloat16* sBh = sAl + 128 * LDS;
    __nv_bfloat16* sBl = sBh + 128 * LDS;

    const int tid = threadIdx.x, lane = tid & 31, wid = tid >> 5;
    const int m0 = blockIdx.y * 128, n0 = blockIdx.x * 128;
    const int wm = (wid & 3) * 32, wn = (wid >> 2) * 64;
    const int g = lane >> 2, tg = lane & 3;
    const int seg = lane >> 3, i8 = lane & 7;

    const uint32_t sAh_b = smem_to_u32(sAh), sAl_b = smem_to_u32(sAl);
    const uint32_t sBh_b = smem_to_u32(sBh), sBl_b = smem_to_u32(sBl);

    float acc[2][8][4];
#pragma unroll
    for (int im = 0; im < 2; im++)
#pragma unroll
        for (int jn = 0; jn < 8; jn++)
#pragma unroll
            for (int q = 0; q < 4; q++) acc[im][jn][q] = 0.f;

    for (int kc = 0; kc < K; kc += 64) {
        if (kc) __syncthreads();
        {
            const __nv_bfloat16* srcs[4] = {Ah, Al, Bh, Bl};
            __nv_bfloat16* dsts[4] = {sAh, sAl, sBh, sBl};
            const int r0s[4] = {m0, m0, n0, n0};
#pragma unroll
            for (int t = 0; t < 4; t++) {
                for (int v = tid; v < 1024; v += 256) {
                    int row = v >> 3, q = (v & 7) * 8;
                    *reinterpret_cast<uint4*>(dsts[t] + row * LDS + q) =
                        *reinterpret_cast<const uint4*>(srcs[t] + (size_t)(r0s[t] + row) * K + kc + q);
                }
            }
        }
        __syncthreads();

#pragma unroll
        for (int ks = 0; ks < 4; ks++) {
            const int k0 = ks * 16;
            uint32_t ah[2][4], al[2][4];
#pragma unroll
            for (int im = 0; im < 2; im++) {
                int arow = wm + im * 16 + (seg & 1) * 8 + i8;
                int acol = k0 + (seg >> 1) * 8;
                LDSM_X4(ah[im], sAh_b + (uint32_t)(arow * LDS + acol) * 2u);
                LDSM_X4(al[im], sAl_b + (uint32_t)(arow * LDS + acol) * 2u);
            }
#pragma unroll
            for (int ip = 0; ip < 4; ip++) {
                int brow = wn + ip * 16 + (seg >> 1) * 8 + i8;
                int bcol = k0 + (seg & 1) * 8;
                uint32_t bh4[4], bl4[4];
                LDSM_X4(bh4, sBh_b + (uint32_t)(brow * LDS + bcol) * 2u);
                LDSM_X4(bl4, sBl_b + (uint32_t)(brow * LDS + bcol) * 2u);
#pragma unroll
                for (int im = 0; im < 2; im++) {
#pragma unroll
                    for (int hf = 0; hf < 2; hf++) {
                        float* c = acc[im][ip * 2 + hf];
                        mma16816(c, ah[im], bh4[2 * hf], bh4[2 * hf + 1]);
                        mma16816(c, al[im], bh4[2 * hf], bh4[2 * hf + 1]);
                        mma16816(c, ah[im], bl4[2 * hf], bl4[2 * hf + 1]);
                    }
                }
            }
        }
    }

#pragma unroll
    for (int im = 0; im < 2; im++) {
#pragma unroll
        for (int jn = 0; jn < 8; jn++) {
            int col = n0 + wn + jn * 8 + tg * 2;
            float b0v = bias[col], b1v = bias[col + 1];
            int row0 = m0 + wm + im * 16 + g;
            float2 v0 = make_float2(acc[im][jn][0] + b0v, acc[im][jn][1] + b1v);
            float2 v1 = make_float2(acc[im][jn][2] + b0v, acc[im][jn][3] + b1v);
            *reinterpret_cast<float2*>(C + (size_t)row0 * Ntot + col) = v0;
            *reinterpret_cast<float2*>(C + (size_t)(row0 + 8) * Ntot + col) = v1;
        }
    }
}

// ================= persistent BiLSTM: FFMA2 inner loop + double-buffered Wh^T =================
__device__ __forceinline__ float sigm(float x) { return 1.f / (1.f + expf(-x)); }

template <int MODE, int TSTEPS, int NSEQ, int ROWS, int THREADS>
__global__ __launch_bounds__(THREADS) void k_lstm(
    const int* __restrict__ idxmat,
    const float* __restrict__ tab_f, const float* __restrict__ tab_b,
    const float* __restrict__ bias_f, const float* __restrict__ bias_b,
    __nv_bfloat16* __restrict__ Hh, __nv_bfloat16* __restrict__ Hl)
{
    constexpr int NW = THREADS / 32, RPT = ROWS / NW;
    constexpr int N4 = 2048 / THREADS;          // float4 per thread per chunk prefetch
    extern __shared__ char dsm[];
    float* hs    = reinterpret_cast<float*>(dsm);       // [ROWS][HH]
    float* wst   = hs + ROWS * HH;                      // [2][16*G4]
    float* sbias = wst + 2 * 16 * G4;                   // [G4]
    int* slen = reinterpret_cast<int*>(sbias + G4);
    int* sfe = slen + ROWS; int* soff = sfe + ROWS; int* sun = soff + ROWS;

    const int dir = blockIdx.y;
    const float* __restrict__ tab = dir ? tab_b : tab_f;
    const float* __restrict__ WhT = g_WhT[2 * MODE + dir];
    const int n0 = blockIdx.x * ROWS;
    const int tid = threadIdx.x, jt = tid & 31, rt = tid >> 5;
    const int e0 = jt * 4, r0 = rt * RPT;

    if (MODE == 1) {
        const float* b = dir ? bias_b : bias_f;
        for (int i = tid; i < G4; i += THREADS) sbias[i] = b[i];
    }
    float c[RPT][4];
#pragma unroll
    for (int r = 0; r < RPT; r++) {
#pragma unroll
        for (int u = 0; u < 4; u++) c[r][u] = 0.f;
        *reinterpret_cast<float4*>(&hs[(r0 + r) * HH + e0]) = make_float4(0.f, 0.f, 0.f, 0.f);
    }
    if (tid < ROWS) {
        int n = n0 + tid;
        slen[tid] = MODE ? g_p_len[n] : g_tok_len[n];
        if (MODE) { sfe[tid] = g_p_fe[n]; soff[tid] = g_p_off[n]; sun[tid] = g_p_un[n]; }
    }
    // preload chunk 0 into buffer 0
#pragma unroll
    for (int t = 0; t < N4; t++) {
        int i = tid + t * THREADS;
        reinterpret_cast<float4*>(wst)[i] = reinterpret_cast<const float4*>(WhT)[i];
    }
    __syncthreads();

    for (int s = 0; s < TSTEPS; s++) {
        u64 acc64[RPT][8];
#pragma unroll
        for (int r = 0; r < RPT; r++)
#pragma unroll
            for (int j = 0; j < 8; j++) acc64[r][j] = 0ull;

#pragma unroll
        for (int ch = 0; ch < 8; ch++) {
            const float* wcur = wst + (ch & 1) * (16 * G4);
            float* wnxt = wst + ((ch + 1) & 1) * (16 * G4);
            const int nxt = (ch + 1) & 7;
            // issue prefetch LDGs for next chunk (same weights every step; buffers rotate)
            float4 pre[N4];
#pragma unroll
            for (int t = 0; t < N4; t++)
                pre[t] = reinterpret_cast<const float4*>(WhT)[nxt * 2048 + tid + t * THREADS];

#pragma unroll
            for (int kk = 0; kk < 16; kk++) {
                ulonglong2 wA = *reinterpret_cast<const ulonglong2*>(&wcur[kk * G4 + e0]);
                ulonglong2 wB = *reinterpret_cast<const ulonglong2*>(&wcur[kk * G4 + 128 + e0]);
                ulonglong2 wC = *reinterpret_cast<const ulonglong2*>(&wcur[kk * G4 + 256 + e0]);
                ulonglong2 wD = *reinterpret_cast<const ulonglong2*>(&wcur[kk * G4 + 384 + e0]);
#pragma unroll
                for (int r = 0; r < RPT; r++) {
                    u64 h2 = dup2(hs[(r0 + r) * HH + ch * 16 + kk]);
                    ffma2(acc64[r][0], h2, wA.x); ffma2(acc64[r][1], h2, wA.y);
                    ffma2(acc64[r][2], h2, wB.x); ffma2(acc64[r][3], h2, wB.y);
                    ffma2(acc64[r][4], h2, wC.x); ffma2(acc64[r][5], h2, wC.y);
                    ffma2(acc64[r][6], h2, wD.x); ffma2(acc64[r][7], h2, wD.y);
                }
            }
            // store prefetched chunk into the other buffer
#pragma unroll
            for (int t = 0; t < N4; t++)
                reinterpret_cast<float4*>(wnxt)[tid + t * THREADS] = pre[t];
            __syncthreads();
        }

        float hnew[RPT][4];
#pragma unroll
        for (int r = 0; r < RPT; r++) {
            // unpack accumulators: j pairs -> 16 gate values
            float a16[16];
#pragma unroll
            for (int j = 0; j < 8; j++) {
                float2 v = unpack2(acc64[r][j]);
                a16[j * 2] = v.x; a16[j * 2 + 1] = v.y;
            }
            int rr = r0 + r, n = n0 + rr, len = slen[rr];
            int gi = dir ? min(max(len - 1 - s, 0), TSTEPS - 1) : s;
            float gv[16];
            if (MODE == 0) {
                int id = idxmat[(size_t)gi * NSEQ + n];
                const float* grow = tab + (size_t)id * G4;
                float4 a0 = *reinterpret_cast<const float4*>(&grow[e0]);
                float4 a1 = *reinterpret_cast<const float4*>(&grow[128 + e0]);
                float4 a2 = *reinterpret_cast<const float4*>(&grow[256 + e0]);
                float4 a3 = *reinterpret_cast<const float4*>(&grow[384 + e0]);
                gv[0]=a0.x; gv[1]=a0.y; gv[2]=a0.z; gv[3]=a0.w;
                gv[4]=a1.x; gv[5]=a1.y; gv[6]=a1.z; gv[7]=a1.w;
                gv[8]=a2.x; gv[9]=a2.y; gv[10]=a2.z; gv[11]=a2.w;
                gv[12]=a3.x; gv[13]=a3.y; gv[14]=a3.z; gv[15]=a3.w;
            } else {
                int pl = idxmat[(size_t)gi * NSEQ + n];
                bool keep = (gi < sfe[rr]) && (pl >= 0) && (pl < sun[rr]);
                float4 b0 = *reinterpret_cast<const float4*>(&sbias[e0]);
                float4 b1 = *reinterpret_cast<const float4*>(&sbias[128 + e0]);
                float4 b2 = *reinterpret_cast<const float4*>(&sbias[256 + e0]);
                float4 b3 = *reinterpret_cast<const float4*>(&sbias[384 + e0]);
                gv[0]=b0.x; gv[1]=b0.y; gv[2]=b0.z; gv[3]=b0.w;
                gv[4]=b1.x; gv[5]=b1.y; gv[6]=b1.z; gv[7]=b1.w;
                gv[8]=b2.x; gv[9]=b2.y; gv[10]=b2.z; gv[11]=b2.w;
                gv[12]=b3.x; gv[13]=b3.y; gv[14]=b3.z; gv[15]=b3.w;
                if (keep) {
                    int gidx = min(pl + soff[rr], NU - 1);
                    const float* grow = tab + (size_t)gidx * G4;
                    float4 t0 = *reinterpret_cast<const float4*>(&grow[e0]);
                    float4 t1 = *reinterpret_cast<const float4*>(&grow[128 + e0]);
                    float4 t2 = *reinterpret_cast<const float4*>(&grow[256 + e0]);
                    float4 t3 = *reinterpret_cast<const float4*>(&grow[384 + e0]);
                    gv[0]+=t0.x; gv[1]+=t0.y; gv[2]+=t0.z; gv[3]+=t0.w;
                    gv[4]+=t1.x; gv[5]+=t1.y; gv[6]+=t1.z; gv[7]+=t1.w;
                    gv[8]+=t2.x; gv[9]+=t2.y; gv[10]+=t2.z; gv[11]+=t2.w;
                    gv[12]+=t3.x; gv[13]+=t3.y; gv[14]+=t3.z; gv[15]+=t3.w;
                }
            }
#pragma unroll
            for (int u = 0; u < 4; u++) {
                float iv = a16[u]      + gv[u];
                float fv = a16[4 + u]  + gv[4 + u];
                float gg = a16[8 + u]  + gv[8 + u];
                float ov = a16[12 + u] + gv[12 + u];
                float cn = sigm(fv) * c[r][u] + sigm(iv) * tanhf(gg);
                c[r][u] = cn;
                hnew[r][u] = sigm(ov) * tanhf(cn);
            }
            if (s < len) {
                int wi = dir ? (len - 1 - s) : s;
                size_t base = ((size_t)wi * NSEQ + n) * (2 * HH) + dir * HH + e0;
                __nv_bfloat16 hb[4], lb[4];
#pragma unroll
                for (int u = 0; u < 4; u++) {
                    hb[u] = __float2bfloat16(hnew[r][u]);
                    lb[u] = __float2bfloat16(hnew[r][u] - __bfloat162float(hb[u]));
                }
                *reinterpret_cast<uint2*>(Hh + base) = *reinterpret_cast<uint2*>(hb);
                *reinterpret_cast<uint2*>(Hl + base) = *reinterpret_cast<uint2*>(lb);
            } else if (dir == 0) {
                uint2 z = make_uint2(0u, 0u);
                size_t b0 = ((size_t)s * NSEQ + n) * (2 * HH) + e0;
                *reinterpret_cast<uint2*>(Hh + b0) = z;
                *reinterpret_cast<uint2*>(Hl + b0) = z;
                *reinterpret_cast<uint2*>(Hh + b0 + HH) = z;
                *reinterpret_cast<uint2*>(Hl + b0 + HH) = z;
            }
        }
        __syncthreads();
#pragma unroll
        for (int r = 0; r < RPT; r++)
            *reinterpret_cast<float4*>(&hs[(r0 + r) * HH + e0]) =
                make_float4(hnew[r][0], hnew[r][1], hnew[r][2], hnew[r][3]);
        __syncthreads();
    }
}

// ================= attention pooling (writes tf hi/lo) =================
__global__ void k_attn(const float* __restrict__ ln_g, const float* __restrict__ ln_b,
                       const float* __restrict__ attn_w, const float* __restrict__ attn_bp) {
    int gwarp = (blockIdx.x * blockDim.x + threadIdx.x) >> 5;
    int lane = threadIdx.x & 31;
    if (gwarp >= NU) return;
    int n = gwarp, len = g_tok_len[n];

    float gg[4], bb[4], aw[4];
#pragma unroll
    for (int q = 0; q < 4; q++) {
        int e = lane + 32 * q;
        gg[q] = ln_g[e]; bb[q] = ln_b[e]; aw[q] = attn_w[e];
    }
    float ab = attn_bp[0];

    float sc[TT], smax = -1e30f;
#pragma unroll
    for (int t = 0; t < TT; t++) {
        sc[t] = -1e30f;
        if (t < len) {
            float o[4], lsum = 0.f;
#pragma unroll
            for (int q = 0; q < 4; q++) {
                o[q] = g_lin[((size_t)t * NU + n) * EE + lane + 32 * q];
                lsum += o[q];
            }
#pragma unroll
            for (int off = 16; off; off >>= 1) lsum += __shfl_xor_sync(0xffffffffu, lsum, off);
            float mean = lsum * (1.f / 128.f);
            float vs = 0.f;
#pragma unroll
            for (int q = 0; q < 4; q++) { float d = o[q] - mean; vs += d * d; }
#pragma unroll
            for (int off = 16; off; off >>= 1) vs += __shfl_xor_sync(0xffffffffu, vs, off);
            float inv = rsqrtf(vs * (1.f / 128.f) + 1e-5f);
            float ssum = 0.f;
#pragma unroll
            for (int q = 0; q < 4; q++)
                ssum += tanhf((o[q] - mean) * inv * gg[q] + bb[q]) * aw[q];
#pragma unroll
            for (int off = 16; off; off >>= 1) ssum += __shfl_xor_sync(0xffffffffu, ssum, off);
            sc[t] = ssum + ab;
            smax = fmaxf(smax, sc[t]);
        }
    }
    float den = 0.f, wts[TT];
#pragma unroll
    for (int t = 0; t < TT; t++) {
        wts[t] = (t < len) ? expf(sc[t] - smax) : 0.f;
        den += wts[t];
    }
    float invden = 1.f / den;
    float accq[4] = {0.f, 0.f, 0.f, 0.f};
#pragma unroll
    for (int t = 0; t < TT; t++) {
        if (t < len) {
            float wt = wts[t] * invden;
#pragma unroll
            for (int q = 0; q < 4; q++)
                accq[q] += wt * g_lin[((size_t)t * NU + n) * EE + lane + 32 * q];
        }
    }
#pragma unroll
    for (int q = 0; q < 4; q++) {
        __nv_bfloat16 h = __float2bfloat16(accq[q]);
        __nv_bfloat16 l = __float2bfloat16(accq[q] - __bfloat162float(h));
        g_tf_h[(size_t)n * EE + lane + 32 * q] = h;
        g_tf_l[(size_t)n * EE + lane + 32 * q] = l;
    }
}

// ================= host launcher =================
extern "C" void kernel_launch(void* const* d_in, const int* in_sizes, int n_in,
                              void* d_out, int out_size) {
    const int*   units  = (const int*)d_in[0];
    const int*   paths  = (const int*)d_in[1];
    const int*   upd    = (const int*)d_in[2];
    const int*   ppd    = (const int*)d_in[3];
    const float* emb    = (const float*)d_in[4];
    const float* tl_Wif = (const float*)d_in[5];
    const float* tl_Whf = (const float*)d_in[6];
    const float* tl_bf  = (const float*)d_in[7];
    const float* tl_Wib = (const float*)d_in[8];
    const float* tl_Whb = (const float*)d_in[9];
    const float* tl_bb  = (const float*)d_in[10];
    const float* lin_W  = (const float*)d_in[11];
    const float* lin_b  = (const float*)d_in[12];
    const float* ln_g   = (const float*)d_in[13];
    const float* ln_bv  = (const float*)d_in[14];
    const float* attn_w = (const float*)d_in[15];
    const float* attn_b = (const float*)d_in[16];
    const float* pl_Wif = (const float*)d_in[17];
    const float* pl_Whf = (const float*)d_in[18];
    const float* pl_bf  = (const float*)d_in[19];
    const float* pl_Wib = (const float*)d_in[20];
    const float* pl_Whb = (const float*)d_in[21];
    const float* pl_bb  = (const float*)d_in[22];
    const float* ul_W   = (const float*)d_in[23];
    const float* ul_b   = (const float*)d_in[24];
    float* out = (float*)d_out;

    void *pVTf, *pVTb, *pPTf, *pPTb, *pLin, *pZero;
    cudaGetSymbolAddress(&pVTf, g_VTf);    cudaGetSymbolAddress(&pVTb, g_VTb);
    cudaGetSymbolAddress(&pPTf, g_PTf);    cudaGetSymbolAddress(&pPTb, g_PTb);
    cudaGetSymbolAddress(&pLin, g_lin);    cudaGetSymbolAddress(&pZero, g_zero);
    void *pEh, *pEl, *pHch, *pHcl, *pTfh, *pTfl, *pHph, *pHpl, *pWih, *pWil, *pW2h, *pW2l;
    cudaGetSymbolAddress(&pEh, g_emb_h);   cudaGetSymbolAddress(&pEl, g_emb_l);
    cudaGetSymbolAddress(&pHch, g_Hcat_h); cudaGetSymbolAddress(&pHcl, g_Hcat_l);
    cudaGetSymbolAddress(&pTfh, g_tf_h);   cudaGetSymbolAddress(&pTfl, g_tf_l);
    cudaGetSymbolAddress(&pHph, g_Hp_h);   cudaGetSymbolAddress(&pHpl, g_Hp_l);
    cudaGetSymbolAddress(&pWih, g_Wih);    cudaGetSymbolAddress(&pWil, g_Wil);
    cudaGetSymbolAddress(&pW2h, g_W2h);    cudaGetSymbolAddress(&pW2l, g_W2l);
    __nv_bfloat16* Wih = (__nv_bfloat16*)pWih;  __nv_bfloat16* Wil = (__nv_bfloat16*)pWil;
    __nv_bfloat16* W2h = (__nv_bfloat16*)pW2h;  __nv_bfloat16* W2l = (__nv_bfloat16*)pW2l;

    const int MM_SMEM = 4 * 128 * 72 * 2;   // 73728
    const int LSTM_SMEM_T = 64 * HH * 4 + 2 * 16 * G4 * 4 + G4 * 4 + 4 * 64 * 4;   // ~101.4KB
    const int LSTM_SMEM_P = 16 * HH * 4 + 2 * 16 * G4 * 4 + G4 * 4 + 4 * 16 * 4;   // ~76KB
    cudaFuncSetAttribute(k_mm2<128>, cudaFuncAttributeMaxDynamicSharedMemorySize, MM_SMEM);
    cudaFuncSetAttribute(k_mm2<256>, cudaFuncAttributeMaxDynamicSharedMemorySize, MM_SMEM);
    cudaFuncSetAttribute((const void*)k_lstm<0, TT, NU, 64, 512>,
                         cudaFuncAttributeMaxDynamicSharedMemorySize, LSTM_SMEM_T + 1024);
    cudaFuncSetAttribute((const void*)k_lstm<1, LPATH, NPATH, 16, 256>,
                         cudaFuncAttributeMaxDynamicSharedMemorySize, LSTM_SMEM_P + 1024);

    // setup
    k_tok_len<<<NU / 256, 256>>>(units);
    k_transpose4<<<dim3((G4 * HH + 255) / 256, 4), 256>>>(tl_Whf, tl_Whb, pl_Whf, pl_Whb);
    k_plen<<<NPATH / 256, 256>>>(paths, upd, ppd);

    // weight + emb hi/lo conversions
    k_hilo<<<(G4 * EE / 4 + 255) / 256, 256>>>(tl_Wif, Wih + 0 * G4 * EE, Wil + 0 * G4 * EE, G4 * EE / 4);
    k_hilo<<<(G4 * EE / 4 + 255) / 256, 256>>>(tl_Wib, Wih + 1 * G4 * EE, Wil + 1 * G4 * EE, G4 * EE / 4);
    k_hilo<<<(G4 * EE / 4 + 255) / 256, 256>>>(pl_Wif, Wih + 2 * G4 * EE, Wil + 2 * G4 * EE, G4 * EE / 4);
    k_hilo<<<(G4 * EE / 4 + 255) / 256, 256>>>(pl_Wib, Wih + 3 * G4 * EE, Wil + 3 * G4 * EE, G4 * EE / 4);
    k_hilo<<<(EE * 256 / 4 + 255) / 256, 256>>>(lin_W, W2h + 0, W2l + 0, EE * 256 / 4);
    k_hilo<<<(EE * 256 / 4 + 255) / 256, 256>>>(ul_W, W2h + EE * 256, W2l + EE * 256, EE * 256 / 4);
    k_hilo<<<(VOCAB * EE / 4 + 255) / 256, 256>>>(emb, (__nv_bfloat16*)pEh, (__nv_bfloat16*)pEl, VOCAB * EE / 4);

    // VT = emb @ Wi^T + b  (16384 x 512, K=128)
    k_mm2<128><<<dim3(4, VOCAB / 128), 256, MM_SMEM>>>((const __nv_bfloat16*)pEh, (const __nv_bfloat16*)pEl,
        Wih + 0 * G4 * EE, Wil + 0 * G4 * EE, tl_bf, (float*)pVTf, G4);
    k_mm2<128><<<dim3(4, VOCAB / 128), 256, MM_SMEM>>>((const __nv_bfloat16*)pEh, (const __nv_bfloat16*)pEl,
        Wih + 1 * G4 * EE, Wil + 1 * G4 * EE, tl_bb, (float*)pVTb, G4);

    // token BiLSTM -> Hcat hi/lo
    k_lstm<0, TT, NU, 64, 512><<<dim3(NU / 64, 2), 512, LSTM_SMEM_T>>>(
        units, (const float*)pVTf, (const float*)pVTb, nullptr, nullptr,
        (__nv_bfloat16*)pHch, (__nv_bfloat16*)pHcl);

    // lin = Hcat @ lin_W^T + lin_b  (65536 x 128, K=256)
    k_mm2<256><<<dim3(1, TT * NU / 128), 256, MM_SMEM>>>((const __nv_bfloat16*)pHch, (const __nv_bfloat16*)pHcl,
        W2h + 0, W2l + 0, lin_b, (float*)pLin, EE);

    // attention -> tf hi/lo
    k_attn<<<(NU * 32) / 256, 256>>>(ln_g, ln_bv, attn_w, attn_b);

    // PT = tokfeat @ pl_Wi^T  (4096 x 512, K=128)
    k_mm2<128><<<dim3(4, NU / 128), 256, MM_SMEM>>>((const __nv_bfloat16*)pTfh, (const __nv_bfloat16*)pTfl,
        Wih + 2 * G4 * EE, Wil + 2 * G4 * EE, (const float*)pZero, (float*)pPTf, G4);
    k_mm2<128><<<dim3(4, NU / 128), 256, MM_SMEM>>>((const __nv_bfloat16*)pTfh, (const __nv_bfloat16*)pTfl,
        Wih + 3 * G4 * EE, Wil + 3 * G4 * EE, (const float*)pZero, (float*)pPTb, G4);

    // path BiLSTM -> Hp hi/lo
    k_lstm<1, LPATH, NPATH, 16, 256><<<dim3(NPATH / 16, 2), 256, LSTM_SMEM_P>>>(
        paths, (const float*)pPTf, (const float*)pPTb, pl_bf, pl_bb,
        (__nv_bfloat16*)pHph, (__nv_bfloat16*)pHpl);

    // out = Hp @ ul_W^T + ul_b  (32768 x 128, K=256)
    k_mm2<256><<<dim3(1, LPATH * NPATH / 128), 256, MM_SMEM>>>((const __nv_bfloat16*)pHph, (const __nv_bfloat16*)pHpl,
        W2h + EE * 256, W2l + EE * 256, ul_b, out, EE);
}